// round 9
// baseline (speedup 1.0000x reference)
#include <cuda_runtime.h>
#include <cuda_fp16.h>
#include <cstdint>

#define NN 100000
#define NE 1600000
#define NG 512
#define D  50
#define DE 8
#define DZ 108
#define NOUT 10

// ---------------- device scratch (no runtime allocation allowed) ----------------
// Projection table Ph[n][200] (fp16), interleaved per channel-pair p (p=0..24):
//   halves [4p .. 4p+3]         = Af[2p], Af[2p+1], As[2p], As[2p+1]  (dst part, biases folded)
//   halves [100+4p .. 100+4p+3] = Bf[2p], Bf[2p+1], Bs[2p], Bs[2p+1]  (src part)
__device__ __align__(16) __half g_Ph[(size_t)NN * 200];
__device__ __align__(16) __half g_eah[(size_t)NE * 8];  // fp16 edge_attr (layer-invariant)
__device__ __align__(16) float g_msg[(size_t)NN * D];   // scatter accumulator (kept zeroed)
__device__ __align__(16) float g_h0[(size_t)NN * D];    // ping-pong h buffers
__device__ __align__(16) float g_h1[(size_t)NN * D];
__device__ __align__(16) float g_Bt[200 * 60];          // tf32 weight matrix, Bt[n][k], layer-baked
__device__ float g_poolmax[NG * D];
__device__ float g_poolsum[NG * D];
__device__ int   g_cnt[NG];
__device__ float g_enc[NG * 2 * D];

constexpr float kL2E = 1.4426950408889634f;   // log2(e)
constexpr float kLN2 = 0.6931471805599453f;   // ln(2)

__device__ __forceinline__ float fast_ex2(float x){ float y; asm("ex2.approx.ftz.f32 %0, %1;" : "=f"(y) : "f"(x)); return y; }
__device__ __forceinline__ float fast_lg2(float x){ float y; asm("lg2.approx.ftz.f32 %0, %1;" : "=f"(y) : "f"(x)); return y; }
__device__ __forceinline__ float fast_rcp(float x){ float y; asm("rcp.approx.ftz.f32 %0, %1;" : "=f"(y) : "f"(x)); return y; }

__device__ __forceinline__ float sigm(float x){
  return fast_rcp(1.0f + fast_ex2(-x * kL2E));
}
__device__ __forceinline__ float softp(float x){
  float t = fast_ex2(-fabsf(x) * kL2E);
  return fmaxf(x, 0.0f) + kLN2 * fast_lg2(1.0f + t);
}

__device__ __forceinline__ __half2 u2h(uint32_t u){ return *reinterpret_cast<__half2*>(&u); }
__device__ __forceinline__ uint32_t f2tf32(float v){
  uint32_t r; asm("cvt.rna.tf32.f32 %0, %1;" : "=r"(r) : "f"(v)); return r;
}

// In-device ping-pong selection (layer: 0 -> x->h0, 1 -> h0->h1, 2 -> h1->h0)
__device__ __forceinline__ const float* layer_in(const float* x, int layer){
  if (layer == 0) return x;
  if (layer == 1) return g_h0;
  return g_h1;
}
__device__ __forceinline__ float* layer_out(int layer){
  return (layer == 1) ? g_h1 : g_h0;
}

// ---------------- setup ----------------
__global__ void zero_global_bufs(){
  int i = blockIdx.x * blockDim.x + threadIdx.x;
  int stride = gridDim.x * blockDim.x;
  for (int j = i; j < NG * 2 * D; j += stride) g_enc[j] = 0.0f;
  for (int j = i; j < NG * D; j += stride){ g_poolmax[j] = 0.0f; g_poolsum[j] = 0.0f; }
  if (i < NG) g_cnt[i] = 0;
}

__global__ void count_kernel(const int* __restrict__ batch){
  int i = blockIdx.x * blockDim.x + threadIdx.x;
  if (i < NN) atomicAdd(&g_cnt[batch[i]], 1);
}

// convert edge_attr to fp16 once per launch (2 edges / thread, grid-stride)
__global__ void ea_half_kernel(const float* __restrict__ ea){
  int stride = gridDim.x * blockDim.x;
  for (int i = blockIdx.x * blockDim.x + threadIdx.x; i < NE / 2; i += stride){
    const float4* src = reinterpret_cast<const float4*>(ea + (size_t)i * 16);
    float4 a = __ldg(src), b = __ldg(src + 1), c = __ldg(src + 2), d = __ldg(src + 3);
    __half2 h0 = __floats2half2_rn(a.x, a.y), h1 = __floats2half2_rn(a.z, a.w);
    __half2 h2 = __floats2half2_rn(b.x, b.y), h3 = __floats2half2_rn(b.z, b.w);
    __half2 h4 = __floats2half2_rn(c.x, c.y), h5 = __floats2half2_rn(c.z, c.w);
    __half2 h6 = __floats2half2_rn(d.x, d.y), h7 = __floats2half2_rn(d.z, d.w);
    uint4* dst = reinterpret_cast<uint4*>(g_eah + (size_t)i * 16);
    dst[0] = make_uint4(*reinterpret_cast<uint32_t*>(&h0), *reinterpret_cast<uint32_t*>(&h1),
                        *reinterpret_cast<uint32_t*>(&h2), *reinterpret_cast<uint32_t*>(&h3));
    dst[1] = make_uint4(*reinterpret_cast<uint32_t*>(&h4), *reinterpret_cast<uint32_t*>(&h5),
                        *reinterpret_cast<uint32_t*>(&h6), *reinterpret_cast<uint32_t*>(&h7));
  }
}

// ---------------- per-layer weight bake: g_Bt[n][k] (tf32), output-interleaved ----
__global__ void prep_B_kernel(const float* __restrict__ Wf, const float* __restrict__ Ws){
  int i = blockIdx.x * blockDim.x + threadIdx.x;
  if (i >= 200 * 60) return;
  int n = i / 60, k = i - n * 60;
  float v = 0.0f;
  if (k < 50){
    int p = (n % 100) >> 2, j = n & 3;
    int c = 2 * p + (j & 1);
    const float* W = (j < 2) ? Wf : Ws;
    int koff = (n < 100) ? k : (50 + k);
    v = W[c * DZ + koff];
  }
  reinterpret_cast<uint32_t*>(g_Bt)[i] = f2tf32(v);
}

// ---------------- node projection via tf32 mma.sync ----------------
#define PM_M 128
#define PM_SMEM_BYTES ((128 * 60 + 200 * 60 + 200) * 4)

__global__ void __launch_bounds__(256) proj_mma_kernel(
    const float* __restrict__ x, int layer,
    const float* __restrict__ bf, const float* __restrict__ bs){
  extern __shared__ float sm[];
  float* sA    = sm;                    // [128][60]
  float* sBt   = sm + 128 * 60;         // [200][60]
  float* sBias = sBt + 200 * 60;        // [200]
  int t = threadIdx.x;
  const float* h = layer_in(x, layer);
  int n0 = blockIdx.x * PM_M;

  for (int i = t; i < 128 * 60; i += 256){
    int r = i / 60, k = i - r * 60;
    int node = n0 + r;
    float v = 0.0f;
    if (k < 50 && node < NN) v = h[(size_t)node * D + k];
    reinterpret_cast<uint32_t*>(sA)[i] = f2tf32(v);
  }
  {
    const float4* gB4 = reinterpret_cast<const float4*>(g_Bt);
    float4* sB4 = reinterpret_cast<float4*>(sBt);
    for (int i = t; i < 200 * 60 / 4; i += 256) sB4[i] = gB4[i];
    for (int i = t; i < 200; i += 256){
      float b = 0.0f;
      if (i < 100){
        int c = 2 * (i >> 2) + (i & 1);
        b = (i & 2) ? bs[c] : bf[c];
      }
      sBias[i] = b;
    }
  }
  __syncthreads();

  int w = t >> 5, lane = t & 31, g = lane >> 2, tg = lane & 3;
  const uint32_t* A = reinterpret_cast<const uint32_t*>(sA);
  const uint32_t* B = reinterpret_cast<const uint32_t*>(sBt);
  int r0 = w * 16 + g;

  uint32_t a[14][2];
  #pragma unroll
  for (int ks = 0; ks < 14; ks++){
    int col = 4 * ks + tg;
    a[ks][0] = A[r0 * 60 + col];
    a[ks][1] = A[(r0 + 8) * 60 + col];
  }

  int node0 = n0 + r0;
  int node1 = node0 + 8;

  #pragma unroll 1
  for (int nt = 0; nt < 25; nt++){
    float c0 = 0.f, c1 = 0.f, c2 = 0.f, c3 = 0.f;
    int nb = nt * 8;
    #pragma unroll
    for (int ks = 0; ks < 14; ks++){
      uint32_t b = B[(nb + g) * 60 + 4 * ks + tg];
      asm volatile(
        "mma.sync.aligned.m16n8k4.row.col.f32.tf32.tf32.f32 "
        "{%0,%1,%2,%3}, {%4,%5}, {%6}, {%0,%1,%2,%3};"
        : "+f"(c0), "+f"(c1), "+f"(c2), "+f"(c3)
        : "r"(a[ks][0]), "r"(a[ks][1]), "r"(b));
    }
    int col0 = nb + 2 * tg;
    float2 bias = *reinterpret_cast<const float2*>(&sBias[col0]);
    if (node0 < NN){
      __half2 hv = __floats2half2_rn(c0 + bias.x, c1 + bias.y);
      *reinterpret_cast<uint32_t*>(g_Ph + (size_t)node0 * 200 + col0) =
          *reinterpret_cast<uint32_t*>(&hv);
    }
    if (node1 < NN){
      __half2 hv = __floats2half2_rn(c2 + bias.x, c3 + bias.y);
      *reinterpret_cast<uint32_t*>(g_Ph + (size_t)node1 * 200 + col0) =
          *reinterpret_cast<uint32_t*>(&hv);
    }
  }
}

// ---------------- edge kernel: 4-edge unrolled + index prefetch, HFMA2 ----------
// 250 active threads/block = 10 quad-lanes × 25 channel-pairs. Next-iteration
// edge indices are prefetched during the current iteration's compute, so the
// idx->gather serial chain is broken: gathers issue immediately at iter start.
__global__ void __launch_bounds__(256, 3) edge_kernel(
    const int* __restrict__ ei,
    const float* __restrict__ Wf, const float* __restrict__ Ws){
  int t = threadIdx.x;
  if (t >= 250) return;
  int p  = t % 25;
  int c0 = 2 * p;

  __half2 whf[8], whs[8];
  #pragma unroll
  for (int k = 0; k < 8; k++){
    whf[k] = __floats2half2_rn(Wf[c0 * DZ + 100 + k], Wf[(c0 + 1) * DZ + 100 + k]);
    whs[k] = __floats2half2_rn(Ws[c0 * DZ + 100 + k], Ws[(c0 + 1) * DZ + 100 + k]);
  }

  const __half* Pb = g_Ph;
  int base = blockIdx.x * 10 + t / 25;        // quad-lane in [0, 20000)

  int4 sidx = __ldg(reinterpret_cast<const int4*>(ei + 4 * base));
  int4 didx = __ldg(reinterpret_cast<const int4*>(ei + NE + 4 * base));

  #pragma unroll 1
  for (int j = 0; j < 20; j++){               // 20000 lanes * 20 iters * 4 edges = 1.6M
    int e0 = 4 * (base + j * 20000);

    // gathers for current iteration issue immediately (indices already resident)
    uint2 dG[4], sG[4];
    dG[0] = __ldg(reinterpret_cast<const uint2*>(Pb + (size_t)didx.x * 200 + 4 * p));
    dG[1] = __ldg(reinterpret_cast<const uint2*>(Pb + (size_t)didx.y * 200 + 4 * p));
    dG[2] = __ldg(reinterpret_cast<const uint2*>(Pb + (size_t)didx.z * 200 + 4 * p));
    dG[3] = __ldg(reinterpret_cast<const uint2*>(Pb + (size_t)didx.w * 200 + 4 * p));
    sG[0] = __ldg(reinterpret_cast<const uint2*>(Pb + (size_t)sidx.x * 200 + 100 + 4 * p));
    sG[1] = __ldg(reinterpret_cast<const uint2*>(Pb + (size_t)sidx.y * 200 + 100 + 4 * p));
    sG[2] = __ldg(reinterpret_cast<const uint2*>(Pb + (size_t)sidx.z * 200 + 100 + 4 * p));
    sG[3] = __ldg(reinterpret_cast<const uint2*>(Pb + (size_t)sidx.w * 200 + 100 + 4 * p));

    uint4 eaq[4];
    const uint4* eap = reinterpret_cast<const uint4*>(g_eah + (size_t)e0 * 8);
    eaq[0] = __ldg(eap + 0);
    eaq[1] = __ldg(eap + 1);
    eaq[2] = __ldg(eap + 2);
    eaq[3] = __ldg(eap + 3);

    int dsts[4] = {didx.x, didx.y, didx.z, didx.w};

    // prefetch next iteration's indices (overlaps with gate math below)
    if (j < 19){
      int gn = 4 * (base + (j + 1) * 20000);
      sidx = __ldg(reinterpret_cast<const int4*>(ei + gn));
      didx = __ldg(reinterpret_cast<const int4*>(ei + NE + gn));
    }

    #pragma unroll
    for (int q = 0; q < 4; q++){
      __half2 ea01 = u2h(eaq[q].x), ea23 = u2h(eaq[q].y);
      __half2 ea45 = u2h(eaq[q].z), ea67 = u2h(eaq[q].w);
      __half2 f2 = __hadd2(u2h(dG[q].x), u2h(sG[q].x));
      __half2 s2 = __hadd2(u2h(dG[q].y), u2h(sG[q].y));
      f2 = __hfma2(whf[0], __low2half2(ea01),  f2);  s2 = __hfma2(whs[0], __low2half2(ea01),  s2);
      f2 = __hfma2(whf[1], __high2half2(ea01), f2);  s2 = __hfma2(whs[1], __high2half2(ea01), s2);
      f2 = __hfma2(whf[2], __low2half2(ea23),  f2);  s2 = __hfma2(whs[2], __low2half2(ea23),  s2);
      f2 = __hfma2(whf[3], __high2half2(ea23), f2);  s2 = __hfma2(whs[3], __high2half2(ea23), s2);
      f2 = __hfma2(whf[4], __low2half2(ea45),  f2);  s2 = __hfma2(whs[4], __low2half2(ea45),  s2);
      f2 = __hfma2(whf[5], __high2half2(ea45), f2);  s2 = __hfma2(whs[5], __high2half2(ea45), s2);
      f2 = __hfma2(whf[6], __low2half2(ea67),  f2);  s2 = __hfma2(whs[6], __low2half2(ea67),  s2);
      f2 = __hfma2(whf[7], __high2half2(ea67), f2);  s2 = __hfma2(whs[7], __high2half2(ea67), s2);
      float2 f = __half22float2(f2);
      float2 s = __half22float2(s2);
      float2 m = make_float2(sigm(f.x) * softp(s.x), sigm(f.y) * softp(s.y));
      atomicAdd(reinterpret_cast<float2*>(g_msg + (size_t)dsts[q] * D + c0), m);
    }
  }
}

// ---------------- finalize: residual + ReLU + smem-pooled max/sum ----------------
// batch is SORTED: a 20-node block usually spans 1-2 graphs. Pre-reduce into
// smem slots, flush once per (slot, channel). Also resets g_msg for next layer.
#define FN_NODES 20
#define FN_SLOTS 16
__global__ void __launch_bounds__(1024) finalize_kernel(const float* __restrict__ x, int layer,
                                                        const int* __restrict__ batch){
  __shared__ float s_max[FN_SLOTS][50];
  __shared__ float s_sum[FN_SLOTS][50];
  __shared__ int s_bmin;
  __shared__ unsigned s_used;
  const float* h_in = layer_in(x, layer);
  float* h_out = layer_out(layer);
  int t = threadIdx.x;
  for (int i = t; i < FN_SLOTS * 50; i += 1024){
    (&s_max[0][0])[i] = 0.0f; (&s_sum[0][0])[i] = 0.0f;
  }
  if (t == 0){
    int n0 = blockIdx.x * FN_NODES; if (n0 >= NN) n0 = NN - 1;
    s_bmin = batch[n0]; s_used = 0u;
  }
  __syncthreads();
  int bmin = s_bmin;

  if (t < FN_NODES * 50){
    int nl = t / 50, c = t - nl * 50;
    int n = blockIdx.x * FN_NODES + nl;
    if (n < NN){
      size_t i = (size_t)n * D + c;
      float v = fmaxf(g_msg[i] + h_in[i], 0.0f);
      h_out[i] = v;
      g_msg[i] = 0.0f;                       // reset for next layer / next launch
      int b = batch[n];
      int s = b - bmin;
      if ((unsigned)s < FN_SLOTS){
        atomicMax(reinterpret_cast<int*>(&s_max[s][c]), __float_as_int(v));
        atomicAdd(&s_sum[s][c], v);
        if (c == 0) atomicOr(&s_used, 1u << s);
      } else {
        atomicMax(reinterpret_cast<int*>(&g_poolmax[b * D + c]), __float_as_int(v));
        atomicAdd(&g_poolsum[b * D + c], v);
      }
    }
  }
  __syncthreads();
  unsigned used = s_used;
  for (int i = t; i < FN_SLOTS * 50; i += 1024){
    int s = i / 50, c = i - s * 50;
    if (used & (1u << s)){
      int b = bmin + s;
      float mv = s_max[s][c];
      if (mv > 0.0f) atomicMax(reinterpret_cast<int*>(&g_poolmax[b * D + c]), __float_as_int(mv));
      float sv = s_sum[s][c];
      if (sv != 0.0f) atomicAdd(&g_poolsum[b * D + c], sv);
    }
  }
}

// accumulate pooled features into enc, re-zero pool buffers for next layer
__global__ void acc_enc_kernel(){
  int i = blockIdx.x * blockDim.x + threadIdx.x;
  if (i >= NG * D) return;
  int b = i / D, c = i - b * D;
  g_enc[b * 100 + c]      += g_poolmax[i];
  g_enc[b * 100 + 50 + c] += g_poolsum[i] / fmaxf((float)g_cnt[b], 1.0f);
  g_poolmax[i] = 0.0f;
  g_poolsum[i] = 0.0f;
}

// ---------------- head: linear + log_softmax; emit [logp | enc] ----------------
__global__ void head_kernel(const float* __restrict__ lw, const float* __restrict__ lb,
                            float* __restrict__ out, int out_size){
  int b = blockIdx.x * blockDim.x + threadIdx.x;
  if (b >= NG) return;
  float e[100];
  #pragma unroll
  for (int k = 0; k < 100; k++) e[k] = g_enc[b * 100 + k];
  float lg[NOUT];
  #pragma unroll
  for (int j = 0; j < NOUT; j++){
    float acc = lb[j];
    #pragma unroll
    for (int k = 0; k < 100; k++) acc += e[k] * lw[j * 100 + k];
    lg[j] = acc;
  }
  float mx = lg[0];
  #pragma unroll
  for (int j = 1; j < NOUT; j++) mx = fmaxf(mx, lg[j]);
  float ss = 0.0f;
  #pragma unroll
  for (int j = 0; j < NOUT; j++) ss += fast_ex2((lg[j] - mx) * kL2E);
  float lse = mx + kLN2 * fast_lg2(ss);
  #pragma unroll
  for (int j = 0; j < NOUT; j++) out[b * NOUT + j] = lg[j] - lse;
  if (out_size >= NG * NOUT + NG * 100){
    #pragma unroll 4
    for (int k = 0; k < 100; k++) out[NG * NOUT + b * 100 + k] = e[k];
  }
}

// ---------------- launch (pure kernel launches; graph-capture safe) ----------------
extern "C" void kernel_launch(void* const* d_in, const int* in_sizes, int n_in,
                              void* d_out, int out_size){
  (void)in_sizes; (void)n_in;
  const float* x  = (const float*)d_in[0];
  const int*   ei = (const int*)  d_in[1];
  const float* ea = (const float*)d_in[2];
  const int*   bt = (const int*)  d_in[3];
  const float* Wf = (const float*)d_in[4];
  const float* bf = (const float*)d_in[5];
  const float* Ws = (const float*)d_in[6];
  const float* bs = (const float*)d_in[7];
  const float* lw = (const float*)d_in[8];
  const float* lb = (const float*)d_in[9];
  float* out = (float*)d_out;

  static bool attr_set = false;
  if (!attr_set){
    cudaFuncSetAttribute(proj_mma_kernel,
                         cudaFuncAttributeMaxDynamicSharedMemorySize, PM_SMEM_BYTES);
    attr_set = true;
  }

  zero_global_bufs<<<128, 256>>>();
  count_kernel<<<(NN + 255) / 256, 256>>>(bt);
  ea_half_kernel<<<1024, 256>>>(ea);

  for (int i = 0; i < 3; i++){
    prep_B_kernel<<<(200 * 60 + 255) / 256, 256>>>(Wf + i * D * DZ, Ws + i * D * DZ);
    proj_mma_kernel<<<(NN + PM_M - 1) / PM_M, 256, PM_SMEM_BYTES>>>(x, i, bf + i * D, bs + i * D);
    edge_kernel<<<2000, 256>>>(ei, Wf + i * D * DZ, Ws + i * D * DZ);
    finalize_kernel<<<(NN + FN_NODES - 1) / FN_NODES, 1024>>>(x, i, bt);
    acc_enc_kernel<<<(NG * D + 255) / 256, 256>>>();
  }

  head_kernel<<<(NG + 127) / 128, 128>>>(lw, lb, out, out_size);
}

// round 12
// speedup vs baseline: 1.0413x; 1.0413x over previous
#include <cuda_runtime.h>
#include <cuda_fp16.h>
#include <cstdint>

#define NN 100000
#define NE 1600000
#define NG 512
#define D  50
#define DE 8
#define DZ 108
#define NOUT 10
#define NQUAD (NE / 4)

// ---------------- device scratch (no runtime allocation allowed) ----------------
// Projection table Ph[n][208] (fp16), interleaved per channel-quad q (q=0..12):
//   halves [8q .. 8q+7]         = Af[4q..4q+3], As[4q..4q+3]   (dst part, biases folded)
//   halves [104+8q .. 104+8q+7] = Bf[4q..4q+3], Bs[4q..4q+3]   (src part)
// channels >= 50 are zero padding. Row = 416 bytes (16B-aligned).
__device__ __align__(16) __half g_Ph[(size_t)NN * 208];
__device__ __align__(16) __half g_eah[(size_t)NE * 8];  // fp16 edge_attr (layer-invariant)
__device__ __align__(16) float g_msg[(size_t)NN * 52];  // scatter accumulator, 52-float rows (pad stays 0)
__device__ __align__(16) float g_h0[(size_t)NN * D];    // ping-pong h buffers
__device__ __align__(16) float g_h1[(size_t)NN * D];
__device__ __align__(16) float g_Bt[208 * 60];          // tf32 weight matrix, Bt[n][k], layer-baked
__device__ float g_poolmax[NG * D];
__device__ float g_poolsum[NG * D];
__device__ int   g_cnt[NG];
__device__ float g_enc[NG * 2 * D];

constexpr float kL2E = 1.4426950408889634f;   // log2(e)
constexpr float kLN2 = 0.6931471805599453f;   // ln(2)

__device__ __forceinline__ float fast_ex2(float x){ float y; asm("ex2.approx.ftz.f32 %0, %1;" : "=f"(y) : "f"(x)); return y; }
__device__ __forceinline__ float fast_lg2(float x){ float y; asm("lg2.approx.ftz.f32 %0, %1;" : "=f"(y) : "f"(x)); return y; }
__device__ __forceinline__ float fast_rcp(float x){ float y; asm("rcp.approx.ftz.f32 %0, %1;" : "=f"(y) : "f"(x)); return y; }

__device__ __forceinline__ float sigm(float x){
  return fast_rcp(1.0f + fast_ex2(-x * kL2E));
}
__device__ __forceinline__ float softp(float x){
  float t = fast_ex2(-fabsf(x) * kL2E);
  return fmaxf(x, 0.0f) + kLN2 * fast_lg2(1.0f + t);
}

__device__ __forceinline__ __half2 u2h(uint32_t u){ return *reinterpret_cast<__half2*>(&u); }
__device__ __forceinline__ uint32_t f2tf32(float v){
  uint32_t r; asm("cvt.rna.tf32.f32 %0, %1;" : "=r"(r) : "f"(v)); return r;
}

// In-device ping-pong selection (layer: 0 -> x->h0, 1 -> h0->h1, 2 -> h1->h0)
__device__ __forceinline__ const float* layer_in(const float* x, int layer){
  if (layer == 0) return x;
  if (layer == 1) return g_h0;
  return g_h1;
}
__device__ __forceinline__ float* layer_out(int layer){
  return (layer == 1) ? g_h1 : g_h0;
}

// ---------------- setup ----------------
__global__ void zero_global_bufs(){
  int i = blockIdx.x * blockDim.x + threadIdx.x;
  int stride = gridDim.x * blockDim.x;
  for (int j = i; j < NG * 2 * D; j += stride) g_enc[j] = 0.0f;
  for (int j = i; j < NG * D; j += stride){ g_poolmax[j] = 0.0f; g_poolsum[j] = 0.0f; }
  if (i < NG) g_cnt[i] = 0;
}

__global__ void count_kernel(const int* __restrict__ batch){
  int i = blockIdx.x * blockDim.x + threadIdx.x;
  if (i < NN) atomicAdd(&g_cnt[batch[i]], 1);
}

// convert edge_attr to fp16 once per launch (2 edges / thread, grid-stride)
__global__ void ea_half_kernel(const float* __restrict__ ea){
  int stride = gridDim.x * blockDim.x;
  for (int i = blockIdx.x * blockDim.x + threadIdx.x; i < NE / 2; i += stride){
    const float4* src = reinterpret_cast<const float4*>(ea + (size_t)i * 16);
    float4 a = __ldg(src), b = __ldg(src + 1), c = __ldg(src + 2), d = __ldg(src + 3);
    __half2 h0 = __floats2half2_rn(a.x, a.y), h1 = __floats2half2_rn(a.z, a.w);
    __half2 h2 = __floats2half2_rn(b.x, b.y), h3 = __floats2half2_rn(b.z, b.w);
    __half2 h4 = __floats2half2_rn(c.x, c.y), h5 = __floats2half2_rn(c.z, c.w);
    __half2 h6 = __floats2half2_rn(d.x, d.y), h7 = __floats2half2_rn(d.z, d.w);
    uint4* dst = reinterpret_cast<uint4*>(g_eah + (size_t)i * 16);
    dst[0] = make_uint4(*reinterpret_cast<uint32_t*>(&h0), *reinterpret_cast<uint32_t*>(&h1),
                        *reinterpret_cast<uint32_t*>(&h2), *reinterpret_cast<uint32_t*>(&h3));
    dst[1] = make_uint4(*reinterpret_cast<uint32_t*>(&h4), *reinterpret_cast<uint32_t*>(&h5),
                        *reinterpret_cast<uint32_t*>(&h6), *reinterpret_cast<uint32_t*>(&h7));
  }
}

// ---------------- per-layer weight bake: g_Bt[n][k] (tf32), quad-interleaved ----
// n in [0,104): dst part, k cols [0:50); n in [104,208): src part, k cols [50:100)
// within each part: m = n (or n-104); q = m>>3; j = m&7; channel c = 4q + (j&3);
// matrix = (j<4) ? Wf : Ws.  c >= 50 -> zero row.
__global__ void prep_B_kernel(const float* __restrict__ Wf, const float* __restrict__ Ws){
  int i = blockIdx.x * blockDim.x + threadIdx.x;
  if (i >= 208 * 60) return;
  int n = i / 60, k = i - n * 60;
  float v = 0.0f;
  if (k < 50){
    int m = (n < 104) ? n : (n - 104);
    int q = m >> 3, j = m & 7;
    int c = 4 * q + (j & 3);
    if (c < 50){
      const float* W = (j < 4) ? Wf : Ws;
      int koff = (n < 104) ? k : (50 + k);
      v = W[c * DZ + koff];
    }
  }
  reinterpret_cast<uint32_t*>(g_Bt)[i] = f2tf32(v);
}

// ---------------- node projection via tf32 mma.sync ----------------
// Block: 256 threads (8 warps), tile M=128 nodes x N=208 outputs x K=56 (52 padded).
#define PM_M 128
#define PM_SMEM_BYTES ((128 * 60 + 208 * 60 + 208) * 4)

__global__ void __launch_bounds__(256) proj_mma_kernel(
    const float* __restrict__ x, int layer,
    const float* __restrict__ bf, const float* __restrict__ bs){
  extern __shared__ float sm[];
  float* sA    = sm;                    // [128][60]
  float* sBt   = sm + 128 * 60;         // [208][60]
  float* sBias = sBt + 208 * 60;        // [208]
  int t = threadIdx.x;
  const float* h = layer_in(x, layer);
  int n0 = blockIdx.x * PM_M;

  for (int i = t; i < 128 * 60; i += 256){
    int r = i / 60, k = i - r * 60;
    int node = n0 + r;
    float v = 0.0f;
    if (k < 50 && node < NN) v = h[(size_t)node * D + k];
    reinterpret_cast<uint32_t*>(sA)[i] = f2tf32(v);
  }
  {
    const float4* gB4 = reinterpret_cast<const float4*>(g_Bt);
    float4* sB4 = reinterpret_cast<float4*>(sBt);
    for (int i = t; i < 208 * 60 / 4; i += 256) sB4[i] = gB4[i];
    for (int i = t; i < 208; i += 256){
      float b = 0.0f;
      if (i < 104){
        int q = i >> 3, j = i & 7;
        int c = 4 * q + (j & 3);
        if (c < 50) b = (j < 4) ? bf[c] : bs[c];
      }
      sBias[i] = b;
    }
  }
  __syncthreads();

  int w = t >> 5, lane = t & 31, g = lane >> 2, tg = lane & 3;
  const uint32_t* A = reinterpret_cast<const uint32_t*>(sA);
  const uint32_t* B = reinterpret_cast<const uint32_t*>(sBt);
  int r0 = w * 16 + g;

  uint32_t a[14][2];
  #pragma unroll
  for (int ks = 0; ks < 14; ks++){
    int col = 4 * ks + tg;
    a[ks][0] = A[r0 * 60 + col];
    a[ks][1] = A[(r0 + 8) * 60 + col];
  }

  int node0 = n0 + r0;
  int node1 = node0 + 8;

  #pragma unroll 1
  for (int nt = 0; nt < 26; nt++){
    float c0 = 0.f, c1 = 0.f, c2 = 0.f, c3 = 0.f;
    int nb = nt * 8;
    #pragma unroll
    for (int ks = 0; ks < 14; ks++){
      uint32_t b = B[(nb + g) * 60 + 4 * ks + tg];
      asm volatile(
        "mma.sync.aligned.m16n8k4.row.col.f32.tf32.tf32.f32 "
        "{%0,%1,%2,%3}, {%4,%5}, {%6}, {%0,%1,%2,%3};"
        : "+f"(c0), "+f"(c1), "+f"(c2), "+f"(c3)
        : "r"(a[ks][0]), "r"(a[ks][1]), "r"(b));
    }
    int col0 = nb + 2 * tg;
    float2 bias = *reinterpret_cast<const float2*>(&sBias[col0]);
    if (node0 < NN){
      __half2 hv = __floats2half2_rn(c0 + bias.x, c1 + bias.y);
      *reinterpret_cast<uint32_t*>(g_Ph + (size_t)node0 * 208 + col0) =
          *reinterpret_cast<uint32_t*>(&hv);
    }
    if (node1 < NN){
      __half2 hv = __floats2half2_rn(c2 + bias.x, c3 + bias.y);
      *reinterpret_cast<uint32_t*>(g_Ph + (size_t)node1 * 208 + col0) =
          *reinterpret_cast<uint32_t*>(&hv);
    }
  }
}

// ---------------- edge kernel: 4-channel lanes, 4-edge unrolled, HFMA2 ----------
// 247 active threads/block = 19 quad-lanes × 13 channel-quads. Each thread handles
// channels 4q..4q+3 for 4 consecutive edges: 2 uint4 gathers per edge (half the
// memory instructions of the 2-channel version), one float4 RED per edge.
#define EK_BLOCKS 1250
#define EK_LPB 19
#define EK_LSTRIDE (EK_BLOCKS * EK_LPB)

__global__ void __launch_bounds__(256, 2) edge_kernel(
    const int* __restrict__ ei,
    const float* __restrict__ Wf, const float* __restrict__ Ws){
  int t = threadIdx.x;
  if (t >= 247) return;
  int q  = t % 13;
  int c0 = 4 * q;

  // half2 ea-weights for channel pairs (c0,c0+1) [lo] and (c0+2,c0+3) [hi]
  __half2 wfl[8], wfh[8], wsl[8], wsh[8];
  #pragma unroll
  for (int k = 0; k < 8; k++){
    wfh[k] = __floats2half2_rn(0.f, 0.f);
    wsh[k] = __floats2half2_rn(0.f, 0.f);
  }
  #pragma unroll
  for (int k = 0; k < 8; k++){
    wfl[k] = __floats2half2_rn(Wf[c0 * DZ + 100 + k], Wf[(c0 + 1) * DZ + 100 + k]);
    wsl[k] = __floats2half2_rn(Ws[c0 * DZ + 100 + k], Ws[(c0 + 1) * DZ + 100 + k]);
  }
  if (q < 12){
    #pragma unroll
    for (int k = 0; k < 8; k++){
      wfh[k] = __floats2half2_rn(Wf[(c0 + 2) * DZ + 100 + k], Wf[(c0 + 3) * DZ + 100 + k]);
      wsh[k] = __floats2half2_rn(Ws[(c0 + 2) * DZ + 100 + k], Ws[(c0 + 3) * DZ + 100 + k]);
    }
  }

  const __half* Pb = g_Ph;
  int lane = blockIdx.x * EK_LPB + t / 13;    // quad-lane id in [0, EK_LSTRIDE)

  #pragma unroll 1
  for (int j = 0; j < 17; j++){               // EK_LSTRIDE * 17 >= NQUAD
    int g = lane + j * EK_LSTRIDE;
    if (g >= NQUAD) break;
    int e0 = 4 * g;
    int4 sidx = __ldg(reinterpret_cast<const int4*>(ei + e0));
    int4 didx = __ldg(reinterpret_cast<const int4*>(ei + NE + e0));

    uint4 dG[4], sG[4];
    dG[0] = __ldg(reinterpret_cast<const uint4*>(Pb + (size_t)didx.x * 208 + 8 * q));
    dG[1] = __ldg(reinterpret_cast<const uint4*>(Pb + (size_t)didx.y * 208 + 8 * q));
    dG[2] = __ldg(reinterpret_cast<const uint4*>(Pb + (size_t)didx.z * 208 + 8 * q));
    dG[3] = __ldg(reinterpret_cast<const uint4*>(Pb + (size_t)didx.w * 208 + 8 * q));
    sG[0] = __ldg(reinterpret_cast<const uint4*>(Pb + (size_t)sidx.x * 208 + 104 + 8 * q));
    sG[1] = __ldg(reinterpret_cast<const uint4*>(Pb + (size_t)sidx.y * 208 + 104 + 8 * q));
    sG[2] = __ldg(reinterpret_cast<const uint4*>(Pb + (size_t)sidx.z * 208 + 104 + 8 * q));
    sG[3] = __ldg(reinterpret_cast<const uint4*>(Pb + (size_t)sidx.w * 208 + 104 + 8 * q));

    uint4 ev[4];
    const uint4* eap = reinterpret_cast<const uint4*>(g_eah + (size_t)e0 * 8);
    ev[0] = __ldg(eap + 0);
    ev[1] = __ldg(eap + 1);
    ev[2] = __ldg(eap + 2);
    ev[3] = __ldg(eap + 3);

    int dsts[4] = {didx.x, didx.y, didx.z, didx.w};
    #pragma unroll
    for (int e = 0; e < 4; e++){
      __half2 ea01 = u2h(ev[e].x), ea23 = u2h(ev[e].y);
      __half2 ea45 = u2h(ev[e].z), ea67 = u2h(ev[e].w);
      __half2 fl = __hadd2(u2h(dG[e].x), u2h(sG[e].x));   // Af+Bf (c0,c0+1)
      __half2 fh = __hadd2(u2h(dG[e].y), u2h(sG[e].y));   // Af+Bf (c0+2,c0+3)
      __half2 sl = __hadd2(u2h(dG[e].z), u2h(sG[e].z));   // As+Bs lo
      __half2 sh = __hadd2(u2h(dG[e].w), u2h(sG[e].w));   // As+Bs hi
      #define EA_STEP(i, EH) \
        { __half2 eb = EH; \
          fl = __hfma2(wfl[i], eb, fl); fh = __hfma2(wfh[i], eb, fh); \
          sl = __hfma2(wsl[i], eb, sl); sh = __hfma2(wsh[i], eb, sh); }
      EA_STEP(0, __low2half2(ea01))  EA_STEP(1, __high2half2(ea01))
      EA_STEP(2, __low2half2(ea23))  EA_STEP(3, __high2half2(ea23))
      EA_STEP(4, __low2half2(ea45))  EA_STEP(5, __high2half2(ea45))
      EA_STEP(6, __low2half2(ea67))  EA_STEP(7, __high2half2(ea67))
      #undef EA_STEP
      float2 flo = __half22float2(fl), fhi = __half22float2(fh);
      float2 slo = __half22float2(sl), shi = __half22float2(sh);
      float4 m;
      m.x = sigm(flo.x) * softp(slo.x);
      m.y = sigm(flo.y) * softp(slo.y);
      m.z = sigm(fhi.x) * softp(shi.x);
      m.w = sigm(fhi.y) * softp(shi.y);
      if (q == 12){ m.z = 0.0f; m.w = 0.0f; }   // pad channels 50,51 stay zero
      atomicAdd(reinterpret_cast<float4*>(g_msg + (size_t)dsts[e] * 52 + c0), m);
    }
  }
}

// ---------------- finalize: residual + ReLU + smem-pooled max/sum ----------------
// batch is SORTED: a 10-node block usually spans 1-2 graphs. Pre-reduce into
// smem slots, flush once per (slot, channel). Also resets g_msg for next layer.
#define FN_NODES 10
#define FN_SLOTS 16
__global__ void __launch_bounds__(512) finalize_kernel(const float* __restrict__ x, int layer,
                                                       const int* __restrict__ batch){
  __shared__ float s_max[FN_SLOTS][50];
  __shared__ float s_sum[FN_SLOTS][50];
  __shared__ int s_bmin;
  __shared__ unsigned s_used;
  const float* h_in = layer_in(x, layer);
  float* h_out = layer_out(layer);
  int t = threadIdx.x;
  for (int i = t; i < FN_SLOTS * 50; i += 512){
    (&s_max[0][0])[i] = 0.0f; (&s_sum[0][0])[i] = 0.0f;
  }
  if (t == 0){
    int n0 = blockIdx.x * FN_NODES; if (n0 >= NN) n0 = NN - 1;
    s_bmin = batch[n0]; s_used = 0u;
  }
  __syncthreads();
  int bmin = s_bmin;

  if (t < FN_NODES * 50){
    int nl = t / 50, c = t - nl * 50;
    int n = blockIdx.x * FN_NODES + nl;
    if (n < NN){
      size_t im = (size_t)n * 52 + c;          // g_msg has 52-float rows
      size_t ih = (size_t)n * D + c;
      float v = fmaxf(g_msg[im] + h_in[ih], 0.0f);
      h_out[ih] = v;
      g_msg[im] = 0.0f;                        // reset for next layer / next launch
      int b = batch[n];
      int s = b - bmin;
      if ((unsigned)s < FN_SLOTS){
        atomicMax(reinterpret_cast<int*>(&s_max[s][c]), __float_as_int(v));
        atomicAdd(&s_sum[s][c], v);
        if (c == 0) atomicOr(&s_used, 1u << s);
      } else {
        atomicMax(reinterpret_cast<int*>(&g_poolmax[b * D + c]), __float_as_int(v));
        atomicAdd(&g_poolsum[b * D + c], v);
      }
    }
  }
  __syncthreads();
  unsigned used = s_used;
  for (int i = t; i < FN_SLOTS * 50; i += 512){
    int s = i / 50, c = i - s * 50;
    if (used & (1u << s)){
      int b = bmin + s;
      float mv = s_max[s][c];
      if (mv > 0.0f) atomicMax(reinterpret_cast<int*>(&g_poolmax[b * D + c]), __float_as_int(mv));
      float sv = s_sum[s][c];
      if (sv != 0.0f) atomicAdd(&g_poolsum[b * D + c], sv);
    }
  }
}

// accumulate pooled features into enc, re-zero pool buffers for next layer
__global__ void acc_enc_kernel(){
  int i = blockIdx.x * blockDim.x + threadIdx.x;
  if (i >= NG * D) return;
  int b = i / D, c = i - b * D;
  g_enc[b * 100 + c]      += g_poolmax[i];
  g_enc[b * 100 + 50 + c] += g_poolsum[i] / fmaxf((float)g_cnt[b], 1.0f);
  g_poolmax[i] = 0.0f;
  g_poolsum[i] = 0.0f;
}

// ---------------- head: linear + log_softmax; emit [logp | enc] ----------------
__global__ void head_kernel(const float* __restrict__ lw, const float* __restrict__ lb,
                            float* __restrict__ out, int out_size){
  int b = blockIdx.x * blockDim.x + threadIdx.x;
  if (b >= NG) return;
  float e[100];
  #pragma unroll
  for (int k = 0; k < 100; k++) e[k] = g_enc[b * 100 + k];
  float lg[NOUT];
  #pragma unroll
  for (int j = 0; j < NOUT; j++){
    float acc = lb[j];
    #pragma unroll
    for (int k = 0; k < 100; k++) acc += e[k] * lw[j * 100 + k];
    lg[j] = acc;
  }
  float mx = lg[0];
  #pragma unroll
  for (int j = 1; j < NOUT; j++) mx = fmaxf(mx, lg[j]);
  float ss = 0.0f;
  #pragma unroll
  for (int j = 0; j < NOUT; j++) ss += fast_ex2((lg[j] - mx) * kL2E);
  float lse = mx + kLN2 * fast_lg2(ss);
  #pragma unroll
  for (int j = 0; j < NOUT; j++) out[b * NOUT + j] = lg[j] - lse;
  if (out_size >= NG * NOUT + NG * 100){
    #pragma unroll 4
    for (int k = 0; k < 100; k++) out[NG * NOUT + b * 100 + k] = e[k];
  }
}

// ---------------- launch (pure kernel launches; graph-capture safe) ----------------
extern "C" void kernel_launch(void* const* d_in, const int* in_sizes, int n_in,
                              void* d_out, int out_size){
  (void)in_sizes; (void)n_in;
  const float* x  = (const float*)d_in[0];
  const int*   ei = (const int*)  d_in[1];
  const float* ea = (const float*)d_in[2];
  const int*   bt = (const int*)  d_in[3];
  const float* Wf = (const float*)d_in[4];
  const float* bf = (const float*)d_in[5];
  const float* Ws = (const float*)d_in[6];
  const float* bs = (const float*)d_in[7];
  const float* lw = (const float*)d_in[8];
  const float* lb = (const float*)d_in[9];
  float* out = (float*)d_out;

  static bool attr_set = false;
  if (!attr_set){
    cudaFuncSetAttribute(proj_mma_kernel,
                         cudaFuncAttributeMaxDynamicSharedMemorySize, PM_SMEM_BYTES);
    attr_set = true;
  }

  zero_global_bufs<<<128, 256>>>();
  count_kernel<<<(NN + 255) / 256, 256>>>(bt);
  ea_half_kernel<<<1024, 256>>>(ea);

  for (int i = 0; i < 3; i++){
    prep_B_kernel<<<(208 * 60 + 255) / 256, 256>>>(Wf + i * D * DZ, Ws + i * D * DZ);
    proj_mma_kernel<<<(NN + PM_M - 1) / PM_M, 256, PM_SMEM_BYTES>>>(x, i, bf + i * D, bs + i * D);
    edge_kernel<<<EK_BLOCKS, 256>>>(ei, Wf + i * D * DZ, Ws + i * D * DZ);
    finalize_kernel<<<(NN + FN_NODES - 1) / FN_NODES, 512>>>(x, i, bt);
    acc_enc_kernel<<<(NG * D + 255) / 256, 256>>>();
  }

  head_kernel<<<(NG + 127) / 128, 128>>>(lw, lb, out, out_size);
}

// round 15
// speedup vs baseline: 1.1323x; 1.0874x over previous
#include <cuda_runtime.h>
#include <cuda_fp16.h>
#include <cstdint>

#define NN 100000
#define NE 1600000
#define NG 512
#define D  50
#define DE 8
#define DZ 108
#define NOUT 10

// ---------------- device scratch (no runtime allocation allowed) ----------------
// Projection table Ph[n][200] (fp16), interleaved per channel-pair p (p=0..24):
//   halves [4p .. 4p+3]         = Af[2p], Af[2p+1], As[2p], As[2p+1]  (dst part, biases folded)
//   halves [100+4p .. 100+4p+3] = Bf[2p], Bf[2p+1], Bs[2p], Bs[2p+1]  (src part)
// resubmission r15 of the 2-tile-proj variant (prior rounds died at container
// level before judging; source functionally identical)
__device__ __align__(16) __half g_Ph[(size_t)NN * 200];
__device__ __align__(16) __half g_eah[(size_t)NE * 8];  // fp16 edge_attr (layer-invariant)
__device__ __align__(16) float g_msg[(size_t)NN * D];   // scatter accumulator (kept zeroed)
__device__ __align__(16) float g_h0[(size_t)NN * D];    // ping-pong h buffers
__device__ __align__(16) float g_h1[(size_t)NN * D];
__device__ __align__(16) float g_Bt[200 * 60];          // tf32 weight matrix, Bt[n][k], layer-baked
__device__ float g_poolmax[NG * D];
__device__ float g_poolsum[NG * D];
__device__ int   g_cnt[NG];
__device__ float g_enc[NG * 2 * D];

constexpr float kL2E = 1.4426950408889634f;   // log2(e)
constexpr float kLN2 = 0.6931471805599453f;   // ln(2)

__device__ __forceinline__ float fast_ex2(float x){ float y; asm("ex2.approx.ftz.f32 %0, %1;" : "=f"(y) : "f"(x)); return y; }
__device__ __forceinline__ float fast_lg2(float x){ float y; asm("lg2.approx.ftz.f32 %0, %1;" : "=f"(y) : "f"(x)); return y; }
__device__ __forceinline__ float fast_rcp(float x){ float y; asm("rcp.approx.ftz.f32 %0, %1;" : "=f"(y) : "f"(x)); return y; }

__device__ __forceinline__ float sigm(float x){
  return fast_rcp(1.0f + fast_ex2(-x * kL2E));
}
__device__ __forceinline__ float softp(float x){
  float t = fast_ex2(-fabsf(x) * kL2E);
  return fmaxf(x, 0.0f) + kLN2 * fast_lg2(1.0f + t);
}

__device__ __forceinline__ __half2 u2h(uint32_t u){ return *reinterpret_cast<__half2*>(&u); }
__device__ __forceinline__ uint32_t f2tf32(float v){
  uint32_t r; asm("cvt.rna.tf32.f32 %0, %1;" : "=r"(r) : "f"(v)); return r;
}

// In-device ping-pong selection (layer: 0 -> x->h0, 1 -> h0->h1, 2 -> h1->h0)
__device__ __forceinline__ const float* layer_in(const float* x, int layer){
  if (layer == 0) return x;
  if (layer == 1) return g_h0;
  return g_h1;
}
__device__ __forceinline__ float* layer_out(int layer){
  return (layer == 1) ? g_h1 : g_h0;
}

// ---------------- setup ----------------
__global__ void zero_global_bufs(){
  int i = blockIdx.x * blockDim.x + threadIdx.x;
  int stride = gridDim.x * blockDim.x;
  for (int j = i; j < NG * 2 * D; j += stride) g_enc[j] = 0.0f;
  for (int j = i; j < NG * D; j += stride){ g_poolmax[j] = 0.0f; g_poolsum[j] = 0.0f; }
  if (i < NG) g_cnt[i] = 0;
}

__global__ void count_kernel(const int* __restrict__ batch){
  int i = blockIdx.x * blockDim.x + threadIdx.x;
  if (i < NN) atomicAdd(&g_cnt[batch[i]], 1);
}

// convert edge_attr to fp16 once per launch (2 edges / thread, grid-stride)
__global__ void ea_half_kernel(const float* __restrict__ ea){
  int stride = gridDim.x * blockDim.x;
  for (int i = blockIdx.x * blockDim.x + threadIdx.x; i < NE / 2; i += stride){
    const float4* src = reinterpret_cast<const float4*>(ea + (size_t)i * 16);
    float4 a = __ldg(src), b = __ldg(src + 1), c = __ldg(src + 2), d = __ldg(src + 3);
    __half2 h0 = __floats2half2_rn(a.x, a.y), h1 = __floats2half2_rn(a.z, a.w);
    __half2 h2 = __floats2half2_rn(b.x, b.y), h3 = __floats2half2_rn(b.z, b.w);
    __half2 h4 = __floats2half2_rn(c.x, c.y), h5 = __floats2half2_rn(c.z, c.w);
    __half2 h6 = __floats2half2_rn(d.x, d.y), h7 = __floats2half2_rn(d.z, d.w);
    uint4* dst = reinterpret_cast<uint4*>(g_eah + (size_t)i * 16);
    dst[0] = make_uint4(*reinterpret_cast<uint32_t*>(&h0), *reinterpret_cast<uint32_t*>(&h1),
                        *reinterpret_cast<uint32_t*>(&h2), *reinterpret_cast<uint32_t*>(&h3));
    dst[1] = make_uint4(*reinterpret_cast<uint32_t*>(&h4), *reinterpret_cast<uint32_t*>(&h5),
                        *reinterpret_cast<uint32_t*>(&h6), *reinterpret_cast<uint32_t*>(&h7));
  }
}

// ---------------- per-layer weight bake: g_Bt[n][k] (tf32), output-interleaved ----
// n in [0,100): dst part, k cols [0:50); n in [100,200): src part, k cols [50:100)
// n%4: 0 -> Wf[2p], 1 -> Wf[2p+1], 2 -> Ws[2p], 3 -> Ws[2p+1]   (p = (n%100)/4)
__global__ void prep_B_kernel(const float* __restrict__ Wf, const float* __restrict__ Ws){
  int i = blockIdx.x * blockDim.x + threadIdx.x;
  if (i >= 200 * 60) return;
  int n = i / 60, k = i - n * 60;
  float v = 0.0f;
  if (k < 50){
    int p = (n % 100) >> 2, j = n & 3;
    int c = 2 * p + (j & 1);
    const float* W = (j < 2) ? Wf : Ws;
    int koff = (n < 100) ? k : (50 + k);
    v = W[c * DZ + koff];
  }
  reinterpret_cast<uint32_t*>(g_Bt)[i] = f2tf32(v);
}

// ---------------- node projection via tf32 mma.sync ----------------
// Block: 256 threads (8 warps), 2 M-tiles of 128 nodes each (256 nodes/block).
// sBt/sBias staged ONCE and reused for both tiles; sA restaged between tiles.
#define PM_M 256
#define PM_SMEM_BYTES ((128 * 60 + 200 * 60 + 200) * 4)

__global__ void __launch_bounds__(256) proj_mma_kernel(
    const float* __restrict__ x, int layer,
    const float* __restrict__ bf, const float* __restrict__ bs){
  extern __shared__ float sm[];
  float* sA    = sm;                    // [128][60]
  float* sBt   = sm + 128 * 60;         // [200][60]
  float* sBias = sBt + 200 * 60;        // [200]
  int t = threadIdx.x;
  const float* h = layer_in(x, layer);

  // stage Bt (pre-baked) and bias once per block
  {
    const float4* gB4 = reinterpret_cast<const float4*>(g_Bt);
    float4* sB4 = reinterpret_cast<float4*>(sBt);
    for (int i = t; i < 200 * 60 / 4; i += 256) sB4[i] = gB4[i];
    for (int i = t; i < 200; i += 256){
      float b = 0.0f;
      if (i < 100){
        int c = 2 * (i >> 2) + (i & 1);
        b = (i & 2) ? bs[c] : bf[c];
      }
      sBias[i] = b;
    }
  }

  int w = t >> 5, lane = t & 31, g = lane >> 2, tg = lane & 3;
  const uint32_t* A = reinterpret_cast<const uint32_t*>(sA);
  const uint32_t* B = reinterpret_cast<const uint32_t*>(sBt);
  int r0 = w * 16 + g;

  #pragma unroll 1
  for (int tile = 0; tile < 2; tile++){
    int n0 = blockIdx.x * PM_M + tile * 128;

    // stage A (tf32-converted h rows, zero-padded); fence previous tile's readers
    if (tile > 0) __syncthreads();
    for (int i = t; i < 128 * 60; i += 256){
      int r = i / 60, k = i - r * 60;
      int node = n0 + r;
      float v = 0.0f;
      if (k < 50 && node < NN) v = h[(size_t)node * D + k];
      reinterpret_cast<uint32_t*>(sA)[i] = f2tf32(v);
    }
    __syncthreads();

    uint32_t a[14][2];
    #pragma unroll
    for (int ks = 0; ks < 14; ks++){
      int col = 4 * ks + tg;
      a[ks][0] = A[r0 * 60 + col];
      a[ks][1] = A[(r0 + 8) * 60 + col];
    }

    int node0 = n0 + r0;
    int node1 = node0 + 8;

    #pragma unroll 1
    for (int nt = 0; nt < 25; nt++){
      float c0 = 0.f, c1 = 0.f, c2 = 0.f, c3 = 0.f;
      int nb = nt * 8;
      #pragma unroll
      for (int ks = 0; ks < 14; ks++){
        uint32_t b = B[(nb + g) * 60 + 4 * ks + tg];
        asm volatile(
          "mma.sync.aligned.m16n8k4.row.col.f32.tf32.tf32.f32 "
          "{%0,%1,%2,%3}, {%4,%5}, {%6}, {%0,%1,%2,%3};"
          : "+f"(c0), "+f"(c1), "+f"(c2), "+f"(c3)
          : "r"(a[ks][0]), "r"(a[ks][1]), "r"(b));
      }
      int col0 = nb + 2 * tg;
      float2 bias = *reinterpret_cast<const float2*>(&sBias[col0]);
      if (node0 < NN){
        __half2 hv = __floats2half2_rn(c0 + bias.x, c1 + bias.y);
        *reinterpret_cast<uint32_t*>(g_Ph + (size_t)node0 * 200 + col0) =
            *reinterpret_cast<uint32_t*>(&hv);
      }
      if (node1 < NN){
        __half2 hv = __floats2half2_rn(c2 + bias.x, c3 + bias.y);
        *reinterpret_cast<uint32_t*>(g_Ph + (size_t)node1 * 200 + col0) =
            *reinterpret_cast<uint32_t*>(&hv);
      }
    }
  }
}

// ---------------- edge kernel: gather-gate-scatter, 4-edge unrolled, HFMA2 ----------
// 250 active threads/block = 10 quad-lanes × 25 channel-pairs. Each thread handles
// 4 consecutive edges per iteration: int4 index loads, 8 independent 8B gathers,
// uint4 fp16 ea loads, half2 gate pre-activation math, float2 RED scatter.
__global__ void __launch_bounds__(256, 3) edge_kernel(
    const int* __restrict__ ei,
    const float* __restrict__ Wf, const float* __restrict__ Ws){
  int t = threadIdx.x;
  if (t >= 250) return;
  int p  = t % 25;
  int c0 = 2 * p;

  // packed half2 weights: whf[k] = (Wf[c0][100+k], Wf[c0+1][100+k]); whs likewise
  __half2 whf[8], whs[8];
  #pragma unroll
  for (int k = 0; k < 8; k++){
    whf[k] = __floats2half2_rn(Wf[c0 * DZ + 100 + k], Wf[(c0 + 1) * DZ + 100 + k]);
    whs[k] = __floats2half2_rn(Ws[c0 * DZ + 100 + k], Ws[(c0 + 1) * DZ + 100 + k]);
  }

  const __half* Pb = g_Ph;
  int base = blockIdx.x * 10 + t / 25;        // quad-lane in [0, 20000)

  #pragma unroll 1
  for (int j = 0; j < 20; j++){               // 20000 lanes * 20 iters * 4 edges = 1.6M
    int g  = base + j * 20000;                // quad index in [0, 400000)
    int e0 = 4 * g;
    int4 sidx = __ldg(reinterpret_cast<const int4*>(ei + e0));        // src of 4 edges
    int4 didx = __ldg(reinterpret_cast<const int4*>(ei + NE + e0));   // dst of 4 edges

    uint2 dG[4], sG[4];
    dG[0] = __ldg(reinterpret_cast<const uint2*>(Pb + (size_t)didx.x * 200 + 4 * p));
    dG[1] = __ldg(reinterpret_cast<const uint2*>(Pb + (size_t)didx.y * 200 + 4 * p));
    dG[2] = __ldg(reinterpret_cast<const uint2*>(Pb + (size_t)didx.z * 200 + 4 * p));
    dG[3] = __ldg(reinterpret_cast<const uint2*>(Pb + (size_t)didx.w * 200 + 4 * p));
    sG[0] = __ldg(reinterpret_cast<const uint2*>(Pb + (size_t)sidx.x * 200 + 100 + 4 * p));
    sG[1] = __ldg(reinterpret_cast<const uint2*>(Pb + (size_t)sidx.y * 200 + 100 + 4 * p));
    sG[2] = __ldg(reinterpret_cast<const uint2*>(Pb + (size_t)sidx.z * 200 + 100 + 4 * p));
    sG[3] = __ldg(reinterpret_cast<const uint2*>(Pb + (size_t)sidx.w * 200 + 100 + 4 * p));

    uint4 eaq[4];
    const uint4* eap = reinterpret_cast<const uint4*>(g_eah + (size_t)e0 * 8);
    eaq[0] = __ldg(eap + 0);
    eaq[1] = __ldg(eap + 1);
    eaq[2] = __ldg(eap + 2);
    eaq[3] = __ldg(eap + 3);

    int dsts[4] = {didx.x, didx.y, didx.z, didx.w};
    #pragma unroll
    for (int q = 0; q < 4; q++){
      __half2 ea01 = u2h(eaq[q].x), ea23 = u2h(eaq[q].y);
      __half2 ea45 = u2h(eaq[q].z), ea67 = u2h(eaq[q].w);
      __half2 f2 = __hadd2(u2h(dG[q].x), u2h(sG[q].x));   // Af+Bf (bias folded in Af)
      __half2 s2 = __hadd2(u2h(dG[q].y), u2h(sG[q].y));   // As+Bs
      f2 = __hfma2(whf[0], __low2half2(ea01),  f2);  s2 = __hfma2(whs[0], __low2half2(ea01),  s2);
      f2 = __hfma2(whf[1], __high2half2(ea01), f2);  s2 = __hfma2(whs[1], __high2half2(ea01), s2);
      f2 = __hfma2(whf[2], __low2half2(ea23),  f2);  s2 = __hfma2(whs[2], __low2half2(ea23),  s2);
      f2 = __hfma2(whf[3], __high2half2(ea23), f2);  s2 = __hfma2(whs[3], __high2half2(ea23), s2);
      f2 = __hfma2(whf[4], __low2half2(ea45),  f2);  s2 = __hfma2(whs[4], __low2half2(ea45),  s2);
      f2 = __hfma2(whf[5], __high2half2(ea45), f2);  s2 = __hfma2(whs[5], __high2half2(ea45), s2);
      f2 = __hfma2(whf[6], __low2half2(ea67),  f2);  s2 = __hfma2(whs[6], __low2half2(ea67),  s2);
      f2 = __hfma2(whf[7], __high2half2(ea67), f2);  s2 = __hfma2(whs[7], __high2half2(ea67), s2);
      float2 f = __half22float2(f2);
      float2 s = __half22float2(s2);
      float2 m = make_float2(sigm(f.x) * softp(s.x), sigm(f.y) * softp(s.y));
      atomicAdd(reinterpret_cast<float2*>(g_msg + (size_t)dsts[q] * D + c0), m);
    }
  }
}

// ---------------- finalize: residual + ReLU + smem-pooled max/sum ----------------
#define FN_NODES 10
#define FN_SLOTS 16
__global__ void __launch_bounds__(512) finalize_kernel(const float* __restrict__ x, int layer,
                                                       const int* __restrict__ batch){
  __shared__ float s_max[FN_SLOTS][50];
  __shared__ float s_sum[FN_SLOTS][50];
  __shared__ int s_bmin;
  __shared__ unsigned s_used;
  const float* h_in = layer_in(x, layer);
  float* h_out = layer_out(layer);
  int t = threadIdx.x;
  for (int i = t; i < FN_SLOTS * 50; i += 512){
    (&s_max[0][0])[i] = 0.0f; (&s_sum[0][0])[i] = 0.0f;
  }
  if (t == 0){
    int n0 = blockIdx.x * FN_NODES; if (n0 >= NN) n0 = NN - 1;
    s_bmin = batch[n0]; s_used = 0u;
  }
  __syncthreads();
  int bmin = s_bmin;

  if (t < FN_NODES * 50){
    int nl = t / 50, c = t - nl * 50;
    int n = blockIdx.x * FN_NODES + nl;
    if (n < NN){
      size_t i = (size_t)n * D + c;
      float v = fmaxf(g_msg[i] + h_in[i], 0.0f);
      h_out[i] = v;
      g_msg[i] = 0.0f;                       // reset for next layer / next launch
      int b = batch[n];
      int s = b - bmin;
      if ((unsigned)s < FN_SLOTS){
        atomicMax(reinterpret_cast<int*>(&s_max[s][c]), __float_as_int(v));
        atomicAdd(&s_sum[s][c], v);
        if (c == 0) atomicOr(&s_used, 1u << s);
      } else {
        atomicMax(reinterpret_cast<int*>(&g_poolmax[b * D + c]), __float_as_int(v));
        atomicAdd(&g_poolsum[b * D + c], v);
      }
    }
  }
  __syncthreads();
  unsigned used = s_used;
  for (int i = t; i < FN_SLOTS * 50; i += 512){
    int s = i / 50, c = i - s * 50;
    if (used & (1u << s)){
      int b = bmin + s;
      float mv = s_max[s][c];
      if (mv > 0.0f) atomicMax(reinterpret_cast<int*>(&g_poolmax[b * D + c]), __float_as_int(mv));
      float sv = s_sum[s][c];
      if (sv != 0.0f) atomicAdd(&g_poolsum[b * D + c], sv);
    }
  }
}

// accumulate pooled features into enc, re-zero pool buffers for next layer
__global__ void acc_enc_kernel(){
  int i = blockIdx.x * blockDim.x + threadIdx.x;
  if (i >= NG * D) return;
  int b = i / D, c = i - b * D;
  g_enc[b * 100 + c]      += g_poolmax[i];
  g_enc[b * 100 + 50 + c] += g_poolsum[i] / fmaxf((float)g_cnt[b], 1.0f);
  g_poolmax[i] = 0.0f;
  g_poolsum[i] = 0.0f;
}

// ---------------- head: linear + log_softmax; emit [logp | enc] ----------------
__global__ void head_kernel(const float* __restrict__ lw, const float* __restrict__ lb,
                            float* __restrict__ out, int out_size){
  int b = blockIdx.x * blockDim.x + threadIdx.x;
  if (b >= NG) return;
  float e[100];
  #pragma unroll
  for (int k = 0; k < 100; k++) e[k] = g_enc[b * 100 + k];
  float lg[NOUT];
  #pragma unroll
  for (int j = 0; j < NOUT; j++){
    float acc = lb[j];
    #pragma unroll
    for (int k = 0; k < 100; k++) acc += e[k] * lw[j * 100 + k];
    lg[j] = acc;
  }
  float mx = lg[0];
  #pragma unroll
  for (int j = 1; j < NOUT; j++) mx = fmaxf(mx, lg[j]);
  float ss = 0.0f;
  #pragma unroll
  for (int j = 0; j < NOUT; j++) ss += fast_ex2((lg[j] - mx) * kL2E);
  float lse = mx + kLN2 * fast_lg2(ss);
  #pragma unroll
  for (int j = 0; j < NOUT; j++) out[b * NOUT + j] = lg[j] - lse;
  if (out_size >= NG * NOUT + NG * 100){
    #pragma unroll 4
    for (int k = 0; k < 100; k++) out[NG * NOUT + b * 100 + k] = e[k];
  }
}

// ---------------- launch (pure kernel launches; graph-capture safe) ----------------
extern "C" void kernel_launch(void* const* d_in, const int* in_sizes, int n_in,
                              void* d_out, int out_size){
  (void)in_sizes; (void)n_in;
  const float* x  = (const float*)d_in[0];
  const int*   ei = (const int*)  d_in[1];
  const float* ea = (const float*)d_in[2];
  const int*   bt = (const int*)  d_in[3];
  const float* Wf = (const float*)d_in[4];
  const float* bf = (const float*)d_in[5];
  const float* Ws = (const float*)d_in[6];
  const float* bs = (const float*)d_in[7];
  const float* lw = (const float*)d_in[8];
  const float* lb = (const float*)d_in[9];
  float* out = (float*)d_out;

  static bool attr_set = false;
  if (!attr_set){
    cudaFuncSetAttribute(proj_mma_kernel,
                         cudaFuncAttributeMaxDynamicSharedMemorySize, PM_SMEM_BYTES);
    attr_set = true;
  }

  zero_global_bufs<<<128, 256>>>();
  count_kernel<<<(NN + 255) / 256, 256>>>(bt);
  ea_half_kernel<<<1024, 256>>>(ea);

  for (int i = 0; i < 3; i++){
    prep_B_kernel<<<(200 * 60 + 255) / 256, 256>>>(Wf + i * D * DZ, Ws + i * D * DZ);
    proj_mma_kernel<<<(NN + PM_M - 1) / PM_M, 256, PM_SMEM_BYTES>>>(x, i, bf + i * D, bs + i * D);
    edge_kernel<<<2000, 256>>>(ei, Wf + i * D * DZ, Ws + i * D * DZ);
    finalize_kernel<<<(NN + FN_NODES - 1) / FN_NODES, 512>>>(x, i, bt);
    acc_enc_kernel<<<(NG * D + 255) / 256, 256>>>();
  }

  head_kernel<<<(NG + 127) / 128, 128>>>(lw, lb, out, out_size);
}

// round 16
// speedup vs baseline: 1.1438x; 1.0102x over previous
#include <cuda_runtime.h>
#include <cuda_fp16.h>
#include <cstdint>

#define NN 100000
#define NE 1600000
#define NG 512
#define D  50
#define DE 8
#define DZ 108
#define NOUT 10

// ---------------- device scratch (no runtime allocation allowed) ----------------
// Projection table Ph[n][200] (fp16), interleaved per channel-pair p (p=0..24):
//   halves [4p .. 4p+3]         = Af[2p], Af[2p+1], As[2p], As[2p+1]  (dst part, biases folded)
//   halves [100+4p .. 100+4p+3] = Bf[2p], Bf[2p+1], Bs[2p], Bs[2p+1]  (src part)
__device__ __align__(16) __half g_Ph[(size_t)NN * 200];
__device__ __align__(16) __half g_eah[(size_t)NE * 8];  // fp16 edge_attr (layer-invariant)
__device__ __align__(16) float g_msg[(size_t)NN * D];   // scatter accumulator (kept zeroed)
__device__ __align__(16) float g_h0[(size_t)NN * D];    // ping-pong h buffers
__device__ __align__(16) float g_h1[(size_t)NN * D];
__device__ __align__(16) float g_Bt[200 * 60];          // tf32 weight matrix, Bt[n][k], layer-baked
__device__ float g_poolmax[NG * D];
__device__ float g_poolsum[NG * D];
__device__ int   g_cnt[NG];
__device__ float g_enc[NG * 2 * D];

constexpr float kL2E = 1.4426950408889634f;   // log2(e)
constexpr float kLN2 = 0.6931471805599453f;   // ln(2)

__device__ __forceinline__ float fast_ex2(float x){ float y; asm("ex2.approx.ftz.f32 %0, %1;" : "=f"(y) : "f"(x)); return y; }
__device__ __forceinline__ float fast_lg2(float x){ float y; asm("lg2.approx.ftz.f32 %0, %1;" : "=f"(y) : "f"(x)); return y; }
__device__ __forceinline__ float fast_rcp(float x){ float y; asm("rcp.approx.ftz.f32 %0, %1;" : "=f"(y) : "f"(x)); return y; }

__device__ __forceinline__ float sigm(float x){
  return fast_rcp(1.0f + fast_ex2(-x * kL2E));
}
__device__ __forceinline__ float softp(float x){
  float t = fast_ex2(-fabsf(x) * kL2E);
  return fmaxf(x, 0.0f) + kLN2 * fast_lg2(1.0f + t);
}

__device__ __forceinline__ __half2 u2h(uint32_t u){ return *reinterpret_cast<__half2*>(&u); }
__device__ __forceinline__ uint32_t f2tf32(float v){
  uint32_t r; asm("cvt.rna.tf32.f32 %0, %1;" : "=r"(r) : "f"(v)); return r;
}

// In-device ping-pong selection (layer: 0 -> x->h0, 1 -> h0->h1, 2 -> h1->h0)
__device__ __forceinline__ const float* layer_in(const float* x, int layer){
  if (layer == 0) return x;
  if (layer == 1) return g_h0;
  return g_h1;
}
__device__ __forceinline__ float* layer_out(int layer){
  return (layer == 1) ? g_h1 : g_h0;
}

// ---------------- setup ----------------
__global__ void zero_global_bufs(){
  int i = blockIdx.x * blockDim.x + threadIdx.x;
  int stride = gridDim.x * blockDim.x;
  for (int j = i; j < NG * 2 * D; j += stride) g_enc[j] = 0.0f;
  for (int j = i; j < NG * D; j += stride){ g_poolmax[j] = 0.0f; g_poolsum[j] = 0.0f; }
  if (i < NG) g_cnt[i] = 0;
}

__global__ void count_kernel(const int* __restrict__ batch){
  int i = blockIdx.x * blockDim.x + threadIdx.x;
  if (i < NN) atomicAdd(&g_cnt[batch[i]], 1);
}

// convert edge_attr to fp16 once per launch (2 edges / thread, grid-stride)
__global__ void ea_half_kernel(const float* __restrict__ ea){
  int stride = gridDim.x * blockDim.x;
  for (int i = blockIdx.x * blockDim.x + threadIdx.x; i < NE / 2; i += stride){
    const float4* src = reinterpret_cast<const float4*>(ea + (size_t)i * 16);
    float4 a = __ldg(src), b = __ldg(src + 1), c = __ldg(src + 2), d = __ldg(src + 3);
    __half2 h0 = __floats2half2_rn(a.x, a.y), h1 = __floats2half2_rn(a.z, a.w);
    __half2 h2 = __floats2half2_rn(b.x, b.y), h3 = __floats2half2_rn(b.z, b.w);
    __half2 h4 = __floats2half2_rn(c.x, c.y), h5 = __floats2half2_rn(c.z, c.w);
    __half2 h6 = __floats2half2_rn(d.x, d.y), h7 = __floats2half2_rn(d.z, d.w);
    uint4* dst = reinterpret_cast<uint4*>(g_eah + (size_t)i * 16);
    dst[0] = make_uint4(*reinterpret_cast<uint32_t*>(&h0), *reinterpret_cast<uint32_t*>(&h1),
                        *reinterpret_cast<uint32_t*>(&h2), *reinterpret_cast<uint32_t*>(&h3));
    dst[1] = make_uint4(*reinterpret_cast<uint32_t*>(&h4), *reinterpret_cast<uint32_t*>(&h5),
                        *reinterpret_cast<uint32_t*>(&h6), *reinterpret_cast<uint32_t*>(&h7));
  }
}

// ---------------- per-layer weight bake: g_Bt[n][k] (tf32), output-interleaved ----
// n in [0,100): dst part, k cols [0:50); n in [100,200): src part, k cols [50:100)
// n%4: 0 -> Wf[2p], 1 -> Wf[2p+1], 2 -> Ws[2p], 3 -> Ws[2p+1]   (p = (n%100)/4)
__global__ void prep_B_kernel(const float* __restrict__ Wf, const float* __restrict__ Ws){
  int i = blockIdx.x * blockDim.x + threadIdx.x;
  if (i >= 200 * 60) return;
  int n = i / 60, k = i - n * 60;
  float v = 0.0f;
  if (k < 50){
    int p = (n % 100) >> 2, j = n & 3;
    int c = 2 * p + (j & 1);
    const float* W = (j < 2) ? Wf : Ws;
    int koff = (n < 100) ? k : (50 + k);
    v = W[c * DZ + koff];
  }
  reinterpret_cast<uint32_t*>(g_Bt)[i] = f2tf32(v);
}

// ---------------- node projection via tf32 mma.sync (R8 config) ----------------
#define PM_M 128
#define PM_SMEM_BYTES ((128 * 60 + 200 * 60 + 200) * 4)

__global__ void __launch_bounds__(256) proj_mma_kernel(
    const float* __restrict__ x, int layer,
    const float* __restrict__ bf, const float* __restrict__ bs){
  extern __shared__ float sm[];
  float* sA    = sm;                    // [128][60]
  float* sBt   = sm + 128 * 60;         // [200][60]
  float* sBias = sBt + 200 * 60;        // [200]
  int t = threadIdx.x;
  const float* h = layer_in(x, layer);
  int n0 = blockIdx.x * PM_M;

  for (int i = t; i < 128 * 60; i += 256){
    int r = i / 60, k = i - r * 60;
    int node = n0 + r;
    float v = 0.0f;
    if (k < 50 && node < NN) v = h[(size_t)node * D + k];
    reinterpret_cast<uint32_t*>(sA)[i] = f2tf32(v);
  }
  {
    const float4* gB4 = reinterpret_cast<const float4*>(g_Bt);
    float4* sB4 = reinterpret_cast<float4*>(sBt);
    for (int i = t; i < 200 * 60 / 4; i += 256) sB4[i] = gB4[i];
    for (int i = t; i < 200; i += 256){
      float b = 0.0f;
      if (i < 100){
        int c = 2 * (i >> 2) + (i & 1);
        b = (i & 2) ? bs[c] : bf[c];
      }
      sBias[i] = b;
    }
  }
  __syncthreads();

  int w = t >> 5, lane = t & 31, g = lane >> 2, tg = lane & 3;
  const uint32_t* A = reinterpret_cast<const uint32_t*>(sA);
  const uint32_t* B = reinterpret_cast<const uint32_t*>(sBt);
  int r0 = w * 16 + g;

  uint32_t a[14][2];
  #pragma unroll
  for (int ks = 0; ks < 14; ks++){
    int col = 4 * ks + tg;
    a[ks][0] = A[r0 * 60 + col];
    a[ks][1] = A[(r0 + 8) * 60 + col];
  }

  int node0 = n0 + r0;
  int node1 = node0 + 8;

  #pragma unroll 1
  for (int nt = 0; nt < 25; nt++){
    float c0 = 0.f, c1 = 0.f, c2 = 0.f, c3 = 0.f;
    int nb = nt * 8;
    #pragma unroll
    for (int ks = 0; ks < 14; ks++){
      uint32_t b = B[(nb + g) * 60 + 4 * ks + tg];
      asm volatile(
        "mma.sync.aligned.m16n8k4.row.col.f32.tf32.tf32.f32 "
        "{%0,%1,%2,%3}, {%4,%5}, {%6}, {%0,%1,%2,%3};"
        : "+f"(c0), "+f"(c1), "+f"(c2), "+f"(c3)
        : "r"(a[ks][0]), "r"(a[ks][1]), "r"(b));
    }
    int col0 = nb + 2 * tg;
    float2 bias = *reinterpret_cast<const float2*>(&sBias[col0]);
    if (node0 < NN){
      __half2 hv = __floats2half2_rn(c0 + bias.x, c1 + bias.y);
      *reinterpret_cast<uint32_t*>(g_Ph + (size_t)node0 * 200 + col0) =
          *reinterpret_cast<uint32_t*>(&hv);
    }
    if (node1 < NN){
      __half2 hv = __floats2half2_rn(c2 + bias.x, c3 + bias.y);
      *reinterpret_cast<uint32_t*>(g_Ph + (size_t)node1 * 200 + col0) =
          *reinterpret_cast<uint32_t*>(&hv);
    }
  }
}

// ---------------- edge kernel: 4-edge idx amortization, 2-edge half-passes ----------
// 250 active threads/block = 10 quad-lanes × 25 channel-pairs. int4 index loads
// amortize over 4 edges; gathers/ea/compute run in two passes of 2 edges to keep
// live registers <= 64 so 4 blocks/SM are resident (1024 thr/SM vs 768 at unroll-4).
__global__ void __launch_bounds__(256, 4) edge_kernel(
    const int* __restrict__ ei,
    const float* __restrict__ Wf, const float* __restrict__ Ws){
  int t = threadIdx.x;
  if (t >= 250) return;
  int p  = t % 25;
  int c0 = 2 * p;

  // packed half2 weights: whf[k] = (Wf[c0][100+k], Wf[c0+1][100+k]); whs likewise
  __half2 whf[8], whs[8];
  #pragma unroll
  for (int k = 0; k < 8; k++){
    whf[k] = __floats2half2_rn(Wf[c0 * DZ + 100 + k], Wf[(c0 + 1) * DZ + 100 + k]);
    whs[k] = __floats2half2_rn(Ws[c0 * DZ + 100 + k], Ws[(c0 + 1) * DZ + 100 + k]);
  }

  const __half* Pb = g_Ph;
  int base = blockIdx.x * 10 + t / 25;        // quad-lane in [0, 20000)

  #pragma unroll 1
  for (int j = 0; j < 20; j++){               // 20000 lanes * 20 iters * 4 edges = 1.6M
    int g  = base + j * 20000;                // quad index in [0, 400000)
    int e0 = 4 * g;
    int4 sidx = __ldg(reinterpret_cast<const int4*>(ei + e0));        // src of 4 edges
    int4 didx = __ldg(reinterpret_cast<const int4*>(ei + NE + e0));   // dst of 4 edges
    const uint4* eap = reinterpret_cast<const uint4*>(g_eah + (size_t)e0 * 8);

    int ss[4] = {sidx.x, sidx.y, sidx.z, sidx.w};
    int dd[4] = {didx.x, didx.y, didx.z, didx.w};

    #pragma unroll
    for (int hp = 0; hp < 2; hp++){
      int sA = ss[2*hp], sB = ss[2*hp+1];
      int dA = dd[2*hp], dB = dd[2*hp+1];
      uint2 dGa = __ldg(reinterpret_cast<const uint2*>(Pb + (size_t)dA * 200 + 4 * p));
      uint2 dGb = __ldg(reinterpret_cast<const uint2*>(Pb + (size_t)dB * 200 + 4 * p));
      uint2 sGa = __ldg(reinterpret_cast<const uint2*>(Pb + (size_t)sA * 200 + 100 + 4 * p));
      uint2 sGb = __ldg(reinterpret_cast<const uint2*>(Pb + (size_t)sB * 200 + 100 + 4 * p));
      uint4 eaA = __ldg(eap + 2*hp);
      uint4 eaB = __ldg(eap + 2*hp + 1);

      // ---- edge A ----
      {
        __half2 ea01 = u2h(eaA.x), ea23 = u2h(eaA.y);
        __half2 ea45 = u2h(eaA.z), ea67 = u2h(eaA.w);
        __half2 f2 = __hadd2(u2h(dGa.x), u2h(sGa.x));
        __half2 s2 = __hadd2(u2h(dGa.y), u2h(sGa.y));
        f2 = __hfma2(whf[0], __low2half2(ea01),  f2);  s2 = __hfma2(whs[0], __low2half2(ea01),  s2);
        f2 = __hfma2(whf[1], __high2half2(ea01), f2);  s2 = __hfma2(whs[1], __high2half2(ea01), s2);
        f2 = __hfma2(whf[2], __low2half2(ea23),  f2);  s2 = __hfma2(whs[2], __low2half2(ea23),  s2);
        f2 = __hfma2(whf[3], __high2half2(ea23), f2);  s2 = __hfma2(whs[3], __high2half2(ea23), s2);
        f2 = __hfma2(whf[4], __low2half2(ea45),  f2);  s2 = __hfma2(whs[4], __low2half2(ea45),  s2);
        f2 = __hfma2(whf[5], __high2half2(ea45), f2);  s2 = __hfma2(whs[5], __high2half2(ea45), s2);
        f2 = __hfma2(whf[6], __low2half2(ea67),  f2);  s2 = __hfma2(whs[6], __low2half2(ea67),  s2);
        f2 = __hfma2(whf[7], __high2half2(ea67), f2);  s2 = __hfma2(whs[7], __high2half2(ea67), s2);
        float2 f = __half22float2(f2);
        float2 s = __half22float2(s2);
        float2 m = make_float2(sigm(f.x) * softp(s.x), sigm(f.y) * softp(s.y));
        atomicAdd(reinterpret_cast<float2*>(g_msg + (size_t)dA * D + c0), m);
      }
      // ---- edge B ----
      {
        __half2 ea01 = u2h(eaB.x), ea23 = u2h(eaB.y);
        __half2 ea45 = u2h(eaB.z), ea67 = u2h(eaB.w);
        __half2 f2 = __hadd2(u2h(dGb.x), u2h(sGb.x));
        __half2 s2 = __hadd2(u2h(dGb.y), u2h(sGb.y));
        f2 = __hfma2(whf[0], __low2half2(ea01),  f2);  s2 = __hfma2(whs[0], __low2half2(ea01),  s2);
        f2 = __hfma2(whf[1], __high2half2(ea01), f2);  s2 = __hfma2(whs[1], __high2half2(ea01), s2);
        f2 = __hfma2(whf[2], __low2half2(ea23),  f2);  s2 = __hfma2(whs[2], __low2half2(ea23),  s2);
        f2 = __hfma2(whf[3], __high2half2(ea23), f2);  s2 = __hfma2(whs[3], __high2half2(ea23), s2);
        f2 = __hfma2(whf[4], __low2half2(ea45),  f2);  s2 = __hfma2(whs[4], __low2half2(ea45),  s2);
        f2 = __hfma2(whf[5], __high2half2(ea45), f2);  s2 = __hfma2(whs[5], __high2half2(ea45), s2);
        f2 = __hfma2(whf[6], __low2half2(ea67),  f2);  s2 = __hfma2(whs[6], __low2half2(ea67),  s2);
        f2 = __hfma2(whf[7], __high2half2(ea67), f2);  s2 = __hfma2(whs[7], __high2half2(ea67), s2);
        float2 f = __half22float2(f2);
        float2 s = __half22float2(s2);
        float2 m = make_float2(sigm(f.x) * softp(s.x), sigm(f.y) * softp(s.y));
        atomicAdd(reinterpret_cast<float2*>(g_msg + (size_t)dB * D + c0), m);
      }
    }
  }
}

// ---------------- finalize: residual + ReLU + smem-pooled max/sum ----------------
#define FN_NODES 10
#define FN_SLOTS 16
__global__ void __launch_bounds__(512) finalize_kernel(const float* __restrict__ x, int layer,
                                                       const int* __restrict__ batch){
  __shared__ float s_max[FN_SLOTS][50];
  __shared__ float s_sum[FN_SLOTS][50];
  __shared__ int s_bmin;
  __shared__ unsigned s_used;
  const float* h_in = layer_in(x, layer);
  float* h_out = layer_out(layer);
  int t = threadIdx.x;
  for (int i = t; i < FN_SLOTS * 50; i += 512){
    (&s_max[0][0])[i] = 0.0f; (&s_sum[0][0])[i] = 0.0f;
  }
  if (t == 0){
    int n0 = blockIdx.x * FN_NODES; if (n0 >= NN) n0 = NN - 1;
    s_bmin = batch[n0]; s_used = 0u;
  }
  __syncthreads();
  int bmin = s_bmin;

  if (t < FN_NODES * 50){
    int nl = t / 50, c = t - nl * 50;
    int n = blockIdx.x * FN_NODES + nl;
    if (n < NN){
      size_t i = (size_t)n * D + c;
      float v = fmaxf(g_msg[i] + h_in[i], 0.0f);
      h_out[i] = v;
      g_msg[i] = 0.0f;                       // reset for next layer / next launch
      int b = batch[n];
      int s = b - bmin;
      if ((unsigned)s < FN_SLOTS){
        atomicMax(reinterpret_cast<int*>(&s_max[s][c]), __float_as_int(v));
        atomicAdd(&s_sum[s][c], v);
        if (c == 0) atomicOr(&s_used, 1u << s);
      } else {
        atomicMax(reinterpret_cast<int*>(&g_poolmax[b * D + c]), __float_as_int(v));
        atomicAdd(&g_poolsum[b * D + c], v);
      }
    }
  }
  __syncthreads();
  unsigned used = s_used;
  for (int i = t; i < FN_SLOTS * 50; i += 512){
    int s = i / 50, c = i - s * 50;
    if (used & (1u << s)){
      int b = bmin + s;
      float mv = s_max[s][c];
      if (mv > 0.0f) atomicMax(reinterpret_cast<int*>(&g_poolmax[b * D + c]), __float_as_int(mv));
      float sv = s_sum[s][c];
      if (sv != 0.0f) atomicAdd(&g_poolsum[b * D + c], sv);
    }
  }
}

// accumulate pooled features into enc, re-zero pool buffers for next layer
__global__ void acc_enc_kernel(){
  int i = blockIdx.x * blockDim.x + threadIdx.x;
  if (i >= NG * D) return;
  int b = i / D, c = i - b * D;
  g_enc[b * 100 + c]      += g_poolmax[i];
  g_enc[b * 100 + 50 + c] += g_poolsum[i] / fmaxf((float)g_cnt[b], 1.0f);
  g_poolmax[i] = 0.0f;
  g_poolsum[i] = 0.0f;
}

// ---------------- head: linear + log_softmax; emit [logp | enc] ----------------
__global__ void head_kernel(const float* __restrict__ lw, const float* __restrict__ lb,
                            float* __restrict__ out, int out_size){
  int b = blockIdx.x * blockDim.x + threadIdx.x;
  if (b >= NG) return;
  float e[100];
  #pragma unroll
  for (int k = 0; k < 100; k++) e[k] = g_enc[b * 100 + k];
  float lg[NOUT];
  #pragma unroll
  for (int j = 0; j < NOUT; j++){
    float acc = lb[j];
    #pragma unroll
    for (int k = 0; k < 100; k++) acc += e[k] * lw[j * 100 + k];
    lg[j] = acc;
  }
  float mx = lg[0];
  #pragma unroll
  for (int j = 1; j < NOUT; j++) mx = fmaxf(mx, lg[j]);
  float ss = 0.0f;
  #pragma unroll
  for (int j = 0; j < NOUT; j++) ss += fast_ex2((lg[j] - mx) * kL2E);
  float lse = mx + kLN2 * fast_lg2(ss);
  #pragma unroll
  for (int j = 0; j < NOUT; j++) out[b * NOUT + j] = lg[j] - lse;
  if (out_size >= NG * NOUT + NG * 100){
    #pragma unroll 4
    for (int k = 0; k < 100; k++) out[NG * NOUT + b * 100 + k] = e[k];
  }
}

// ---------------- launch (pure kernel launches; graph-capture safe) ----------------
extern "C" void kernel_launch(void* const* d_in, const int* in_sizes, int n_in,
                              void* d_out, int out_size){
  (void)in_sizes; (void)n_in;
  const float* x  = (const float*)d_in[0];
  const int*   ei = (const int*)  d_in[1];
  const float* ea = (const float*)d_in[2];
  const int*   bt = (const int*)  d_in[3];
  const float* Wf = (const float*)d_in[4];
  const float* bf = (const float*)d_in[5];
  const float* Ws = (const float*)d_in[6];
  const float* bs = (const float*)d_in[7];
  const float* lw = (const float*)d_in[8];
  const float* lb = (const float*)d_in[9];
  float* out = (float*)d_out;

  static bool attr_set = false;
  if (!attr_set){
    cudaFuncSetAttribute(proj_mma_kernel,
                         cudaFuncAttributeMaxDynamicSharedMemorySize, PM_SMEM_BYTES);
    attr_set = true;
  }

  zero_global_bufs<<<128, 256>>>();
  count_kernel<<<(NN + 255) / 256, 256>>>(bt);
  ea_half_kernel<<<1024, 256>>>(ea);

  for (int i = 0; i < 3; i++){
    prep_B_kernel<<<(200 * 60 + 255) / 256, 256>>>(Wf + i * D * DZ, Ws + i * D * DZ);
    proj_mma_kernel<<<(NN + PM_M - 1) / PM_M, 256, PM_SMEM_BYTES>>>(x, i, bf + i * D, bs + i * D);
    edge_kernel<<<2000, 256>>>(ei, Wf + i * D * DZ, Ws + i * D * DZ);
    finalize_kernel<<<(NN + FN_NODES - 1) / FN_NODES, 512>>>(x, i, bt);
    acc_enc_kernel<<<(NG * D + 255) / 256, 256>>>();
  }

  head_kernel<<<(NG + 127) / 128, 128>>>(lw, lb, out, out_size);
}

// round 17
// speedup vs baseline: 1.2149x; 1.0621x over previous
#include <cuda_runtime.h>
#include <cuda_fp16.h>
#include <cstdint>

#define NN 100000
#define NE 1600000
#define NG 512
#define D  50
#define DE 8
#define DZ 108
#define NOUT 10

// ---------------- device scratch (no runtime allocation allowed) ----------------
// Projection table Ph[n][200] (fp16), interleaved per channel-pair p (p=0..24):
//   halves [4p .. 4p+3]         = Af[2p], Af[2p+1], As[2p], As[2p+1]  (dst part, biases folded)
//   halves [100+4p .. 100+4p+3] = Bf[2p], Bf[2p+1], Bs[2p], Bs[2p+1]  (src part)
__device__ __align__(16) __half g_Ph[(size_t)NN * 200];
__device__ __align__(16) __half g_eah[(size_t)NE * 8];  // fp16 edge_attr (layer-invariant)
__device__ __align__(16) float g_msg[(size_t)NN * D];   // scatter accumulator (kept zeroed)
__device__ __align__(16) float g_h0[(size_t)NN * D];    // ping-pong h buffers
__device__ __align__(16) float g_h1[(size_t)NN * D];
__device__ __align__(16) float g_Bt[200 * 60];          // tf32 weight matrix, Bt[n][k], layer-baked
__device__ float g_poolmax[NG * D];
__device__ float g_poolsum[NG * D];
__device__ int   g_cnt[NG];
__device__ float g_enc[NG * 2 * D];

constexpr float kL2E = 1.4426950408889634f;   // log2(e)
constexpr float kLN2 = 0.6931471805599453f;   // ln(2)

__device__ __forceinline__ float fast_ex2(float x){ float y; asm("ex2.approx.ftz.f32 %0, %1;" : "=f"(y) : "f"(x)); return y; }
__device__ __forceinline__ float fast_lg2(float x){ float y; asm("lg2.approx.ftz.f32 %0, %1;" : "=f"(y) : "f"(x)); return y; }
__device__ __forceinline__ float fast_rcp(float x){ float y; asm("rcp.approx.ftz.f32 %0, %1;" : "=f"(y) : "f"(x)); return y; }

__device__ __forceinline__ float sigm(float x){
  return fast_rcp(1.0f + fast_ex2(-x * kL2E));
}
__device__ __forceinline__ float softp(float x){
  float t = fast_ex2(-fabsf(x) * kL2E);
  return fmaxf(x, 0.0f) + kLN2 * fast_lg2(1.0f + t);
}

__device__ __forceinline__ __half2 u2h(uint32_t u){ return *reinterpret_cast<__half2*>(&u); }
__device__ __forceinline__ uint32_t f2tf32(float v){
  uint32_t r; asm("cvt.rna.tf32.f32 %0, %1;" : "=r"(r) : "f"(v)); return r;
}

// In-device ping-pong selection (layer: 0 -> x->h0, 1 -> h0->h1, 2 -> h1->h0)
__device__ __forceinline__ const float* layer_in(const float* x, int layer){
  if (layer == 0) return x;
  if (layer == 1) return g_h0;
  return g_h1;
}
__device__ __forceinline__ float* layer_out(int layer){
  return (layer == 1) ? g_h1 : g_h0;
}

// ---------------- setup ----------------
__global__ void zero_global_bufs(){
  int i = blockIdx.x * blockDim.x + threadIdx.x;
  int stride = gridDim.x * blockDim.x;
  for (int j = i; j < NG * 2 * D; j += stride) g_enc[j] = 0.0f;
  for (int j = i; j < NG * D; j += stride){ g_poolmax[j] = 0.0f; g_poolsum[j] = 0.0f; }
  if (i < NG) g_cnt[i] = 0;
}

__global__ void count_kernel(const int* __restrict__ batch){
  int i = blockIdx.x * blockDim.x + threadIdx.x;
  if (i < NN) atomicAdd(&g_cnt[batch[i]], 1);
}

// convert edge_attr to fp16 once per launch (2 edges / thread, grid-stride)
__global__ void ea_half_kernel(const float* __restrict__ ea){
  int stride = gridDim.x * blockDim.x;
  for (int i = blockIdx.x * blockDim.x + threadIdx.x; i < NE / 2; i += stride){
    const float4* src = reinterpret_cast<const float4*>(ea + (size_t)i * 16);
    float4 a = __ldg(src), b = __ldg(src + 1), c = __ldg(src + 2), d = __ldg(src + 3);
    __half2 h0 = __floats2half2_rn(a.x, a.y), h1 = __floats2half2_rn(a.z, a.w);
    __half2 h2 = __floats2half2_rn(b.x, b.y), h3 = __floats2half2_rn(b.z, b.w);
    __half2 h4 = __floats2half2_rn(c.x, c.y), h5 = __floats2half2_rn(c.z, c.w);
    __half2 h6 = __floats2half2_rn(d.x, d.y), h7 = __floats2half2_rn(d.z, d.w);
    uint4* dst = reinterpret_cast<uint4*>(g_eah + (size_t)i * 16);
    dst[0] = make_uint4(*reinterpret_cast<uint32_t*>(&h0), *reinterpret_cast<uint32_t*>(&h1),
                        *reinterpret_cast<uint32_t*>(&h2), *reinterpret_cast<uint32_t*>(&h3));
    dst[1] = make_uint4(*reinterpret_cast<uint32_t*>(&h4), *reinterpret_cast<uint32_t*>(&h5),
                        *reinterpret_cast<uint32_t*>(&h6), *reinterpret_cast<uint32_t*>(&h7));
  }
}

// ---------------- per-layer weight bake: g_Bt[n][k] (tf32), output-interleaved ----
// n in [0,100): dst part, k cols [0:50); n in [100,200): src part, k cols [50:100)
// n%4: 0 -> Wf[2p], 1 -> Wf[2p+1], 2 -> Ws[2p], 3 -> Ws[2p+1]   (p = (n%100)/4)
__global__ void prep_B_kernel(const float* __restrict__ Wf, const float* __restrict__ Ws){
  int i = blockIdx.x * blockDim.x + threadIdx.x;
  if (i >= 200 * 60) return;
  int n = i / 60, k = i - n * 60;
  float v = 0.0f;
  if (k < 50){
    int p = (n % 100) >> 2, j = n & 3;
    int c = 2 * p + (j & 1);
    const float* W = (j < 2) ? Wf : Ws;
    int koff = (n < 100) ? k : (50 + k);
    v = W[c * DZ + koff];
  }
  reinterpret_cast<uint32_t*>(g_Bt)[i] = f2tf32(v);
}

// ---------------- node projection via tf32 mma.sync (R8 config) ----------------
#define PM_M 128
#define PM_SMEM_BYTES ((128 * 60 + 200 * 60 + 200) * 4)

__global__ void __launch_bounds__(256) proj_mma_kernel(
    const float* __restrict__ x, int layer,
    const float* __restrict__ bf, const float* __restrict__ bs){
  extern __shared__ float sm[];
  float* sA    = sm;                    // [128][60]
  float* sBt   = sm + 128 * 60;         // [200][60]
  float* sBias = sBt + 200 * 60;        // [200]
  int t = threadIdx.x;
  const float* h = layer_in(x, layer);
  int n0 = blockIdx.x * PM_M;

  for (int i = t; i < 128 * 60; i += 256){
    int r = i / 60, k = i - r * 60;
    int node = n0 + r;
    float v = 0.0f;
    if (k < 50 && node < NN) v = h[(size_t)node * D + k];
    reinterpret_cast<uint32_t*>(sA)[i] = f2tf32(v);
  }
  {
    const float4* gB4 = reinterpret_cast<const float4*>(g_Bt);
    float4* sB4 = reinterpret_cast<float4*>(sBt);
    for (int i = t; i < 200 * 60 / 4; i += 256) sB4[i] = gB4[i];
    for (int i = t; i < 200; i += 256){
      float b = 0.0f;
      if (i < 100){
        int c = 2 * (i >> 2) + (i & 1);
        b = (i & 2) ? bs[c] : bf[c];
      }
      sBias[i] = b;
    }
  }
  __syncthreads();

  int w = t >> 5, lane = t & 31, g = lane >> 2, tg = lane & 3;
  const uint32_t* A = reinterpret_cast<const uint32_t*>(sA);
  const uint32_t* B = reinterpret_cast<const uint32_t*>(sBt);
  int r0 = w * 16 + g;

  uint32_t a[14][2];
  #pragma unroll
  for (int ks = 0; ks < 14; ks++){
    int col = 4 * ks + tg;
    a[ks][0] = A[r0 * 60 + col];
    a[ks][1] = A[(r0 + 8) * 60 + col];
  }

  int node0 = n0 + r0;
  int node1 = node0 + 8;

  #pragma unroll 1
  for (int nt = 0; nt < 25; nt++){
    float c0 = 0.f, c1 = 0.f, c2 = 0.f, c3 = 0.f;
    int nb = nt * 8;
    #pragma unroll
    for (int ks = 0; ks < 14; ks++){
      uint32_t b = B[(nb + g) * 60 + 4 * ks + tg];
      asm volatile(
        "mma.sync.aligned.m16n8k4.row.col.f32.tf32.tf32.f32 "
        "{%0,%1,%2,%3}, {%4,%5}, {%6}, {%0,%1,%2,%3};"
        : "+f"(c0), "+f"(c1), "+f"(c2), "+f"(c3)
        : "r"(a[ks][0]), "r"(a[ks][1]), "r"(b));
    }
    int col0 = nb + 2 * tg;
    float2 bias = *reinterpret_cast<const float2*>(&sBias[col0]);
    if (node0 < NN){
      __half2 hv = __floats2half2_rn(c0 + bias.x, c1 + bias.y);
      *reinterpret_cast<uint32_t*>(g_Ph + (size_t)node0 * 200 + col0) =
          *reinterpret_cast<uint32_t*>(&hv);
    }
    if (node1 < NN){
      __half2 hv = __floats2half2_rn(c2 + bias.x, c3 + bias.y);
      *reinterpret_cast<uint32_t*>(g_Ph + (size_t)node1 * 200 + col0) =
          *reinterpret_cast<uint32_t*>(&hv);
    }
  }
}

// ---------------- edge kernel: 4-edge idx amortization, 2-edge half-passes ----------
__global__ void __launch_bounds__(256, 4) edge_kernel(
    const int* __restrict__ ei,
    const float* __restrict__ Wf, const float* __restrict__ Ws){
  int t = threadIdx.x;
  if (t >= 250) return;
  int p  = t % 25;
  int c0 = 2 * p;

  __half2 whf[8], whs[8];
  #pragma unroll
  for (int k = 0; k < 8; k++){
    whf[k] = __floats2half2_rn(Wf[c0 * DZ + 100 + k], Wf[(c0 + 1) * DZ + 100 + k]);
    whs[k] = __floats2half2_rn(Ws[c0 * DZ + 100 + k], Ws[(c0 + 1) * DZ + 100 + k]);
  }

  const __half* Pb = g_Ph;
  int base = blockIdx.x * 10 + t / 25;        // quad-lane in [0, 20000)

  #pragma unroll 1
  for (int j = 0; j < 20; j++){               // 20000 lanes * 20 iters * 4 edges = 1.6M
    int g  = base + j * 20000;
    int e0 = 4 * g;
    int4 sidx = __ldg(reinterpret_cast<const int4*>(ei + e0));
    int4 didx = __ldg(reinterpret_cast<const int4*>(ei + NE + e0));
    const uint4* eap = reinterpret_cast<const uint4*>(g_eah + (size_t)e0 * 8);

    int ss[4] = {sidx.x, sidx.y, sidx.z, sidx.w};
    int dd[4] = {didx.x, didx.y, didx.z, didx.w};

    #pragma unroll
    for (int hp = 0; hp < 2; hp++){
      int sA = ss[2*hp], sB = ss[2*hp+1];
      int dA = dd[2*hp], dB = dd[2*hp+1];
      uint2 dGa = __ldg(reinterpret_cast<const uint2*>(Pb + (size_t)dA * 200 + 4 * p));
      uint2 dGb = __ldg(reinterpret_cast<const uint2*>(Pb + (size_t)dB * 200 + 4 * p));
      uint2 sGa = __ldg(reinterpret_cast<const uint2*>(Pb + (size_t)sA * 200 + 100 + 4 * p));
      uint2 sGb = __ldg(reinterpret_cast<const uint2*>(Pb + (size_t)sB * 200 + 100 + 4 * p));
      uint4 eaA = __ldg(eap + 2*hp);
      uint4 eaB = __ldg(eap + 2*hp + 1);

      {
        __half2 ea01 = u2h(eaA.x), ea23 = u2h(eaA.y);
        __half2 ea45 = u2h(eaA.z), ea67 = u2h(eaA.w);
        __half2 f2 = __hadd2(u2h(dGa.x), u2h(sGa.x));
        __half2 s2 = __hadd2(u2h(dGa.y), u2h(sGa.y));
        f2 = __hfma2(whf[0], __low2half2(ea01),  f2);  s2 = __hfma2(whs[0], __low2half2(ea01),  s2);
        f2 = __hfma2(whf[1], __high2half2(ea01), f2);  s2 = __hfma2(whs[1], __high2half2(ea01), s2);
        f2 = __hfma2(whf[2], __low2half2(ea23),  f2);  s2 = __hfma2(whs[2], __low2half2(ea23),  s2);
        f2 = __hfma2(whf[3], __high2half2(ea23), f2);  s2 = __hfma2(whs[3], __high2half2(ea23), s2);
        f2 = __hfma2(whf[4], __low2half2(ea45),  f2);  s2 = __hfma2(whs[4], __low2half2(ea45),  s2);
        f2 = __hfma2(whf[5], __high2half2(ea45), f2);  s2 = __hfma2(whs[5], __high2half2(ea45), s2);
        f2 = __hfma2(whf[6], __low2half2(ea67),  f2);  s2 = __hfma2(whs[6], __low2half2(ea67),  s2);
        f2 = __hfma2(whf[7], __high2half2(ea67), f2);  s2 = __hfma2(whs[7], __high2half2(ea67), s2);
        float2 f = __half22float2(f2);
        float2 s = __half22float2(s2);
        float2 m = make_float2(sigm(f.x) * softp(s.x), sigm(f.y) * softp(s.y));
        atomicAdd(reinterpret_cast<float2*>(g_msg + (size_t)dA * D + c0), m);
      }
      {
        __half2 ea01 = u2h(eaB.x), ea23 = u2h(eaB.y);
        __half2 ea45 = u2h(eaB.z), ea67 = u2h(eaB.w);
        __half2 f2 = __hadd2(u2h(dGb.x), u2h(sGb.x));
        __half2 s2 = __hadd2(u2h(dGb.y), u2h(sGb.y));
        f2 = __hfma2(whf[0], __low2half2(ea01),  f2);  s2 = __hfma2(whs[0], __low2half2(ea01),  s2);
        f2 = __hfma2(whf[1], __high2half2(ea01), f2);  s2 = __hfma2(whs[1], __high2half2(ea01), s2);
        f2 = __hfma2(whf[2], __low2half2(ea23),  f2);  s2 = __hfma2(whs[2], __low2half2(ea23),  s2);
        f2 = __hfma2(whf[3], __high2half2(ea23), f2);  s2 = __hfma2(whs[3], __high2half2(ea23), s2);
        f2 = __hfma2(whf[4], __low2half2(ea45),  f2);  s2 = __hfma2(whs[4], __low2half2(ea45),  s2);
        f2 = __hfma2(whf[5], __high2half2(ea45), f2);  s2 = __hfma2(whs[5], __high2half2(ea45), s2);
        f2 = __hfma2(whf[6], __low2half2(ea67),  f2);  s2 = __hfma2(whs[6], __low2half2(ea67),  s2);
        f2 = __hfma2(whf[7], __high2half2(ea67), f2);  s2 = __hfma2(whs[7], __high2half2(ea67), s2);
        float2 f = __half22float2(f2);
        float2 s = __half22float2(s2);
        float2 m = make_float2(sigm(f.x) * softp(s.x), sigm(f.y) * softp(s.y));
        atomicAdd(reinterpret_cast<float2*>(g_msg + (size_t)dB * D + c0), m);
      }
    }
  }
}

// ---------------- finalize: residual + ReLU + smem-pooled max/sum ----------------
// batch is SORTED; min graph size ~150, so a 40-node block spans <= 2 graphs.
// 40 nodes/block (4x fewer blocks than before): global pool atomics drop ~4x and
// the fixed smem init/flush cost amortizes over 4x more nodes.
#define FN_NODES 40
#define FN_SLOTS 16
__global__ void __launch_bounds__(512) finalize_kernel(const float* __restrict__ x, int layer,
                                                       const int* __restrict__ batch){
  __shared__ float s_max[FN_SLOTS][50];
  __shared__ float s_sum[FN_SLOTS][50];
  __shared__ int s_bmin;
  __shared__ unsigned s_used;
  const float* h_in = layer_in(x, layer);
  float* h_out = layer_out(layer);
  int t = threadIdx.x;
  for (int i = t; i < FN_SLOTS * 50; i += 512){
    (&s_max[0][0])[i] = 0.0f; (&s_sum[0][0])[i] = 0.0f;
  }
  if (t == 0){
    int n0 = blockIdx.x * FN_NODES; if (n0 >= NN) n0 = NN - 1;
    s_bmin = batch[n0]; s_used = 0u;
  }
  __syncthreads();
  int bmin = s_bmin;

  #pragma unroll 1
  for (int e = t; e < FN_NODES * 50; e += 512){
    int nl = e / 50, c = e - nl * 50;
    int n = blockIdx.x * FN_NODES + nl;
    if (n < NN){
      size_t i = (size_t)n * D + c;
      float v = fmaxf(g_msg[i] + h_in[i], 0.0f);
      h_out[i] = v;
      g_msg[i] = 0.0f;                       // reset for next layer / next launch
      int b = batch[n];
      int s = b - bmin;
      if ((unsigned)s < FN_SLOTS){
        atomicMax(reinterpret_cast<int*>(&s_max[s][c]), __float_as_int(v));
        atomicAdd(&s_sum[s][c], v);
        if (c == 0) atomicOr(&s_used, 1u << s);
      } else {
        atomicMax(reinterpret_cast<int*>(&g_poolmax[b * D + c]), __float_as_int(v));
        atomicAdd(&g_poolsum[b * D + c], v);
      }
    }
  }
  __syncthreads();
  unsigned used = s_used;
  for (int i = t; i < FN_SLOTS * 50; i += 512){
    int s = i / 50, c = i - s * 50;
    if (used & (1u << s)){
      int b = bmin + s;
      float mv = s_max[s][c];
      if (mv > 0.0f) atomicMax(reinterpret_cast<int*>(&g_poolmax[b * D + c]), __float_as_int(mv));
      float sv = s_sum[s][c];
      if (sv != 0.0f) atomicAdd(&g_poolsum[b * D + c], sv);
    }
  }
}

// accumulate pooled features into enc, re-zero pool buffers for next layer
__global__ void acc_enc_kernel(){
  int i = blockIdx.x * blockDim.x + threadIdx.x;
  if (i >= NG * D) return;
  int b = i / D, c = i - b * D;
  g_enc[b * 100 + c]      += g_poolmax[i];
  g_enc[b * 100 + 50 + c] += g_poolsum[i] / fmaxf((float)g_cnt[b], 1.0f);
  g_poolmax[i] = 0.0f;
  g_poolsum[i] = 0.0f;
}

// ---------------- head: linear + log_softmax; emit [logp | enc] ----------------
__global__ void head_kernel(const float* __restrict__ lw, const float* __restrict__ lb,
                            float* __restrict__ out, int out_size){
  int b = blockIdx.x * blockDim.x + threadIdx.x;
  if (b >= NG) return;
  float e[100];
  #pragma unroll
  for (int k = 0; k < 100; k++) e[k] = g_enc[b * 100 + k];
  float lg[NOUT];
  #pragma unroll
  for (int j = 0; j < NOUT; j++){
    float acc = lb[j];
    #pragma unroll
    for (int k = 0; k < 100; k++) acc += e[k] * lw[j * 100 + k];
    lg[j] = acc;
  }
  float mx = lg[0];
  #pragma unroll
  for (int j = 1; j < NOUT; j++) mx = fmaxf(mx, lg[j]);
  float ss = 0.0f;
  #pragma unroll
  for (int j = 0; j < NOUT; j++) ss += fast_ex2((lg[j] - mx) * kL2E);
  float lse = mx + kLN2 * fast_lg2(ss);
  #pragma unroll
  for (int j = 0; j < NOUT; j++) out[b * NOUT + j] = lg[j] - lse;
  if (out_size >= NG * NOUT + NG * 100){
    #pragma unroll 4
    for (int k = 0; k < 100; k++) out[NG * NOUT + b * 100 + k] = e[k];
  }
}

// ---------------- launch (pure kernel launches; graph-capture safe) ----------------
extern "C" void kernel_launch(void* const* d_in, const int* in_sizes, int n_in,
                              void* d_out, int out_size){
  (void)in_sizes; (void)n_in;
  const float* x  = (const float*)d_in[0];
  const int*   ei = (const int*)  d_in[1];
  const float* ea = (const float*)d_in[2];
  const int*   bt = (const int*)  d_in[3];
  const float* Wf = (const float*)d_in[4];
  const float* bf = (const float*)d_in[5];
  const float* Ws = (const float*)d_in[6];
  const float* bs = (const float*)d_in[7];
  const float* lw = (const float*)d_in[8];
  const float* lb = (const float*)d_in[9];
  float* out = (float*)d_out;

  static bool attr_set = false;
  if (!attr_set){
    cudaFuncSetAttribute(proj_mma_kernel,
                         cudaFuncAttributeMaxDynamicSharedMemorySize, PM_SMEM_BYTES);
    attr_set = true;
  }

  zero_global_bufs<<<128, 256>>>();
  count_kernel<<<(NN + 255) / 256, 256>>>(bt);
  ea_half_kernel<<<1024, 256>>>(ea);

  for (int i = 0; i < 3; i++){
    prep_B_kernel<<<(200 * 60 + 255) / 256, 256>>>(Wf + i * D * DZ, Ws + i * D * DZ);
    proj_mma_kernel<<<(NN + PM_M - 1) / PM_M, 256, PM_SMEM_BYTES>>>(x, i, bf + i * D, bs + i * D);
    edge_kernel<<<2000, 256>>>(ei, Wf + i * D * DZ, Ws + i * D * DZ);
    finalize_kernel<<<(NN + FN_NODES - 1) / FN_NODES, 512>>>(x, i, bt);
    acc_enc_kernel<<<(NG * D + 255) / 256, 256>>>();
  }

  head_kernel<<<(NG + 127) / 128, 128>>>(lw, lb, out, out_size);
}